// round 1
// baseline (speedup 1.0000x reference)
#include <cuda_runtime.h>
#include <math.h>

// Problem constants (fixed shapes from reference setup_inputs)
#define P   8192     // number of pairs (rows and cols of logits)
#define D   256      // feature dim
#define BM  64       // rows per block
#define BN  64       // key-chunk width
#define RS  260      // padded smem row stride in floats (256 + 4 -> 16B-aligned, conflict-spread)
#define NCE_INV_T (1.0f/0.07f)

// Scratch (device globals: allocation-free)
__device__ float g_Q[P*D];       // gathered queries f1[map21]
__device__ float g_qsq[P];
__device__ float g_ksq[P];
__device__ float g_rowloss[P];
__device__ int   g_is64;

typedef unsigned long long u64;

__device__ __forceinline__ u64 ffma2(u64 a, u64 b, u64 c){
    u64 d;
    asm("fma.rn.f32x2 %0, %1, %2, %3;" : "=l"(d) : "l"(a), "l"(b), "l"(c));
    return d;
}
__device__ __forceinline__ float unpack_sum(u64 a){
    float lo, hi;
    asm("mov.b64 {%0, %1}, %2;" : "=f"(lo), "=f"(hi) : "l"(a));
    return lo + hi;
}

// ---------------------------------------------------------------------------
// Detect whether map21 arrived as int64 or int32.
// Reads only the first 8192 int32 words (32KB) -- valid in BOTH cases.
// If int64: those words are (lo,hi) pairs with hi==0 (values in [0,20000)),
// so all odd words are zero. If int32: odd words are random indices,
// essentially surely nonzero somewhere.
// ---------------------------------------------------------------------------
__global__ void detect_kernel(const int* __restrict__ m32){
    __shared__ int nz;
    if (threadIdx.x == 0) nz = 0;
    __syncthreads();
    int any = 0;
    for (int i = 1 + 2*(int)threadIdx.x; i < P; i += 2*(int)blockDim.x)
        if (m32[i] != 0) any = 1;
    if (any) atomicOr(&nz, 1);
    __syncthreads();
    if (threadIdx.x == 0) g_is64 = (nz == 0) ? 1 : 0;
}

// ---------------------------------------------------------------------------
// Gather Q = f1[map21], and precompute squared norms of Q rows and K rows.
// One block per row, 256 threads (= D).
// ---------------------------------------------------------------------------
__global__ void gather_kernel(const float* __restrict__ f1,
                              const float* __restrict__ f2,
                              const void*  __restrict__ map){
    const int row = blockIdx.x;
    const int t   = threadIdx.x;
    long long idx = g_is64 ? ((const long long*)map)[row]
                           : (long long)((const int*)map)[row];
    float q = f1[idx * (long long)D + t];
    float k = f2[(long long)row * D + t];
    g_Q[row * D + t] = q;
    float qs = q*q, ks = k*k;
    #pragma unroll
    for (int o = 16; o; o >>= 1){
        qs += __shfl_xor_sync(0xffffffffu, qs, o);
        ks += __shfl_xor_sync(0xffffffffu, ks, o);
    }
    __shared__ float sq[8], sk[8];
    int w = t >> 5, l = t & 31;
    if (l == 0){ sq[w] = qs; sk[w] = ks; }
    __syncthreads();
    if (t == 0){
        float a = 0.f, b = 0.f;
        #pragma unroll
        for (int i = 0; i < 8; i++){ a += sq[i]; b += sk[i]; }
        g_qsq[row] = a;
        g_ksq[row] = b;
    }
}

// ---------------------------------------------------------------------------
// Main flash-style kernel: 128 blocks x 256 threads (16x16).
// Each block owns 64 rows; streams 128 key chunks of 64 cols.
// Thread (tx,ty) computes a 4x4 micro-tile: rows ty+16r, cols tx+16c
// (strided so smem reads are broadcast/conflict-light).
// Accumulation uses packed fp32x2 FMA (2x scalar FFMA throughput).
// Per-row online logsumexp across the 16 lanes sharing a row.
// ---------------------------------------------------------------------------
extern __shared__ float smem[];

__global__ __launch_bounds__(256, 1)
void nce_main_kernel(const float* __restrict__ keys){
    float* Qs    = smem;                  // BM * RS floats
    float* Ks    = smem + BM * RS;        // BN * RS floats
    float* ksq_s = smem + 2 * BM * RS;    // BN floats

    const int tid = threadIdx.x;
    const int tx = tid & 15, ty = tid >> 4;
    const int m0 = blockIdx.x * BM;

    // Load Q tile once (vectorized, coalesced)
    for (int i = tid; i < BM * (D/4); i += 256){
        int m  = i >> 6;          // D/4 == 64 float4 per row
        int kv = i & 63;
        float4 v = reinterpret_cast<const float4*>(g_Q)[(m0 + m) * (D/4) + kv];
        *reinterpret_cast<float4*>(&Qs[m * RS + kv * 4]) = v;
    }

    float qsq[4], m_run[4], s_run[4], diag[4];
    #pragma unroll
    for (int r = 0; r < 4; r++){
        qsq[r]   = g_qsq[m0 + ty + 16*r];
        m_run[r] = -INFINITY;
        s_run[r] = 0.f;
        diag[r]  = -INFINITY;
    }

    for (int cb = 0; cb < P/BN; ++cb){
        const int c0 = cb * BN;
        __syncthreads();   // protect Ks/ksq_s from previous iteration's readers
        for (int i = tid; i < BN * (D/4); i += 256){
            int c  = i >> 6;
            int kv = i & 63;
            float4 v = reinterpret_cast<const float4*>(keys)[(c0 + c) * (D/4) + kv];
            *reinterpret_cast<float4*>(&Ks[c * RS + kv * 4]) = v;
        }
        if (tid < BN) ksq_s[tid] = g_ksq[c0 + tid];
        __syncthreads();

        u64 acc[4][4];
        #pragma unroll
        for (int r = 0; r < 4; r++)
            #pragma unroll
            for (int c = 0; c < 4; c++) acc[r][c] = 0ull;

        #pragma unroll 2
        for (int kk = 0; kk < D/4; ++kk){
            ulonglong2 qv[4], kvv[4];
            #pragma unroll
            for (int r = 0; r < 4; r++)
                qv[r] = *reinterpret_cast<const ulonglong2*>(&Qs[(ty + 16*r) * RS + kk * 4]);
            #pragma unroll
            for (int c = 0; c < 4; c++)
                kvv[c] = *reinterpret_cast<const ulonglong2*>(&Ks[(tx + 16*c) * RS + kk * 4]);
            #pragma unroll
            for (int r = 0; r < 4; r++)
                #pragma unroll
                for (int c = 0; c < 4; c++){
                    acc[r][c] = ffma2(qv[r].x, kvv[c].x, acc[r][c]);
                    acc[r][c] = ffma2(qv[r].y, kvv[c].y, acc[r][c]);
                }
        }

        // Epilogue: logits for this 64-wide chunk + online logsumexp per row
        #pragma unroll
        for (int r = 0; r < 4; r++){
            float l[4];
            float cmax = -INFINITY;
            const int grow = m0 + ty + 16*r;
            #pragma unroll
            for (int c = 0; c < 4; c++){
                const int lc = tx + 16*c;
                float dot = unpack_sum(acc[r][c]);
                float sqd = qsq[r] + ksq_s[lc] - 2.f * dot;
                sqd = fmaxf(sqd, 0.f);
                float lg = -sqrtf(sqd) * NCE_INV_T;
                l[c] = lg;
                if (c0 + lc == grow) diag[r] = lg;
                cmax = fmaxf(cmax, lg);
            }
            #pragma unroll
            for (int o = 1; o < 16; o <<= 1)
                cmax = fmaxf(cmax, __shfl_xor_sync(0xffffffffu, cmax, o));
            float newm = fmaxf(m_run[r], cmax);
            float p = __expf(l[0]-newm) + __expf(l[1]-newm)
                    + __expf(l[2]-newm) + __expf(l[3]-newm);
            #pragma unroll
            for (int o = 1; o < 16; o <<= 1)
                p += __shfl_xor_sync(0xffffffffu, p, o);
            // clamp avoids (-inf - newm) -> exp producing anything odd on chunk 0
            s_run[r] = s_run[r] * __expf(fmaxf(m_run[r] - newm, -80.f)) + p;
            m_run[r] = newm;
        }
    }

    // Row result: lse - diag  (all 16 lanes of a row hold identical m,s)
    #pragma unroll
    for (int r = 0; r < 4; r++){
        float d = diag[r];
        #pragma unroll
        for (int o = 1; o < 16; o <<= 1)
            d = fmaxf(d, __shfl_xor_sync(0xffffffffu, d, o));
        if (tx == 0){
            int grow = m0 + ty + 16*r;
            g_rowloss[grow] = (m_run[r] + logf(s_run[r])) - d;
        }
    }
}

// ---------------------------------------------------------------------------
// Final mean reduction
// ---------------------------------------------------------------------------
__global__ void mean_kernel(float* __restrict__ out){
    float a = 0.f;
    for (int i = threadIdx.x; i < P; i += 256) a += g_rowloss[i];
    #pragma unroll
    for (int o = 16; o; o >>= 1) a += __shfl_xor_sync(0xffffffffu, a, o);
    __shared__ float sw[8];
    int w = threadIdx.x >> 5;
    if ((threadIdx.x & 31) == 0) sw[w] = a;
    __syncthreads();
    if (threadIdx.x == 0){
        float t = 0.f;
        #pragma unroll
        for (int i = 0; i < 8; i++) t += sw[i];
        out[0] = t / (float)P;
    }
}

extern "C" void kernel_launch(void* const* d_in, const int* in_sizes, int n_in,
                              void* d_out, int out_size){
    const float* f1  = (const float*)d_in[0];   // [1,20000,256] f32
    const float* f2  = (const float*)d_in[1];   // [1,8192,256]  f32
    const void*  map = d_in[2];                 // [8192] int64 or int32

    const int SMEM_BYTES = (2 * BM * RS + BN) * (int)sizeof(float);  // 133,376 B
    cudaFuncSetAttribute(nce_main_kernel,
                         cudaFuncAttributeMaxDynamicSharedMemorySize, SMEM_BYTES);

    detect_kernel<<<1, 256>>>((const int*)map);
    gather_kernel<<<P, 256>>>(f1, f2, map);
    nce_main_kernel<<<P/BM, 256, SMEM_BYTES>>>(f2);
    mean_kernel<<<1, 256>>>((float*)d_out);
}

// round 3
// speedup vs baseline: 2.6850x; 2.6850x over previous
#include <cuda_runtime.h>
#include <cuda_bf16.h>
#include <stdint.h>
#include <math.h>

#define P 8192
#define D 256
#define C_L2T 20.60992915555662f   // log2(e)/0.07
#define LN2F  0.6931471805599453f

// ---------------- device scratch (allocation-free) ----------------
__device__ int g_is64;
__device__ __align__(16) uint32_t g_Qhi[P * 128];   // bf16x2 packed, row-major [row][128]
__device__ __align__(16) uint32_t g_Qlo[P * 128];
__device__ __align__(16) uint32_t g_Khi[P * 128];
__device__ __align__(16) uint32_t g_Klo[P * 128];
__device__ float g_qsq[P];
__device__ float g_ksq[P];
__device__ float g_pm[P * 2];
__device__ float g_ps[P * 2];
__device__ float g_pd[P];

// ---------------- smem layout (bytes) ----------------
// Q rows stride 528B (264 bf16): 528 % 128 == 16 -> ldmatrix conflict-free
#define OFF_QH   0
#define OFF_QL   67584          // 128*528
#define OFF_KH   135168
#define OFF_KL   168960         // +64*528
#define OFF_KSQ  202752         // 2 slots x 256B
#define OFF_PART 203264         // float2[2][2][64] = 2048B
#define SMEM_TOTAL 205312

// ---------------- PTX helpers (base-PTX only, sm_103-safe) ----------------
__device__ __forceinline__ uint32_t smem_u32(const void* p){
    uint32_t a;
    asm("{ .reg .u64 t; cvta.to.shared.u64 t, %1; cvt.u32.u64 %0, t; }" : "=r"(a) : "l"(p));
    return a;
}
__device__ __forceinline__ void cpa16(uint32_t dst, const void* src){
    asm volatile("cp.async.cg.shared.global [%0], [%1], 16;" :: "r"(dst), "l"(src));
}
#define CP_COMMIT asm volatile("cp.async.commit_group;" ::: "memory")
#define CP_WAIT0  asm volatile("cp.async.wait_group 0;" ::: "memory")

__device__ __forceinline__ void ldm_x4(uint32_t& r0, uint32_t& r1, uint32_t& r2, uint32_t& r3,
                                       uint32_t addr){
    asm volatile("ldmatrix.sync.aligned.m8n8.x4.shared.b16 {%0,%1,%2,%3}, [%4];"
                 : "=r"(r0), "=r"(r1), "=r"(r2), "=r"(r3) : "r"(addr));
}
__device__ __forceinline__ void mma_bf16(float c[4], const uint32_t a[4],
                                         uint32_t b0, uint32_t b1){
    asm volatile(
        "mma.sync.aligned.m16n8k16.row.col.f32.bf16.bf16.f32 "
        "{%0,%1,%2,%3}, {%4,%5,%6,%7}, {%8,%9}, {%0,%1,%2,%3};"
        : "+f"(c[0]), "+f"(c[1]), "+f"(c[2]), "+f"(c[3])
        : "r"(a[0]), "r"(a[1]), "r"(a[2]), "r"(a[3]), "r"(b0), "r"(b1));
}
__device__ __forceinline__ float ex2a(float x){ float y; asm("ex2.approx.f32 %0, %1;" : "=f"(y) : "f"(x)); return y; }
__device__ __forceinline__ float sqrta(float x){ float y; asm("sqrt.approx.f32 %0, %1;" : "=f"(y) : "f"(x)); return y; }

__device__ __forceinline__ uint32_t f2bf_bits(float x){
    return (uint32_t)__bfloat16_as_ushort(__float2bfloat16(x));
}
__device__ __forceinline__ float bf_bits2f(uint32_t b){
    return __bfloat162float(__ushort_as_bfloat16((unsigned short)b));
}

// ---------------- 1: dtype detection (int64 vs int32 map) ----------------
__global__ void detect_kernel(const int* __restrict__ m32){
    __shared__ int nz;
    if (threadIdx.x == 0) nz = 0;
    __syncthreads();
    int any = 0;
    for (int i = 1 + 2*(int)threadIdx.x; i < P; i += 2*(int)blockDim.x)
        if (m32[i] != 0) any = 1;
    if (any) atomicOr(&nz, 1);
    __syncthreads();
    if (threadIdx.x == 0) g_is64 = (nz == 0) ? 1 : 0;
}

// ---------------- 2: gather Q, split hi/lo, qsq ----------------
__global__ void prepQ_kernel(const float* __restrict__ f1, const void* __restrict__ map){
    const int r = blockIdx.x, t = threadIdx.x;
    long long idx = g_is64 ? ((const long long*)map)[r]
                           : (long long)((const int*)map)[r];
    float2 q = reinterpret_cast<const float2*>(f1 + idx * (long long)D)[t];
    uint32_t hx = f2bf_bits(q.x), hy = f2bf_bits(q.y);
    g_Qhi[r*128 + t] = hx | (hy << 16);
    uint32_t lx = f2bf_bits(q.x - bf_bits2f(hx));
    uint32_t ly = f2bf_bits(q.y - bf_bits2f(hy));
    g_Qlo[r*128 + t] = lx | (ly << 16);
    float qs = q.x*q.x + q.y*q.y;
    #pragma unroll
    for (int o = 16; o; o >>= 1) qs += __shfl_xor_sync(0xffffffffu, qs, o);
    __shared__ float sw[4];
    if ((t & 31) == 0) sw[t >> 5] = qs;
    __syncthreads();
    if (t == 0) g_qsq[r] = sw[0] + sw[1] + sw[2] + sw[3];
}

// ---------------- 3/4: K hi / K lo packing ----------------
__global__ void prepKhi_kernel(const float* __restrict__ f2){
    const int r = blockIdx.x, t = threadIdx.x;
    float2 k = reinterpret_cast<const float2*>(f2 + (long long)r * D)[t];
    uint32_t hx = f2bf_bits(k.x), hy = f2bf_bits(k.y);
    g_Khi[r*128 + t] = hx | (hy << 16);
}
__global__ void prepKlo_kernel(const float* __restrict__ f2){
    const int r = blockIdx.x, t = threadIdx.x;
    float2 k = reinterpret_cast<const float2*>(f2 + (long long)r * D)[t];
    uint32_t hx = f2bf_bits(k.x), hy = f2bf_bits(k.y);
    uint32_t lx = f2bf_bits(k.x - bf_bits2f(hx));
    uint32_t ly = f2bf_bits(k.y - bf_bits2f(hy));
    g_Klo[r*128 + t] = lx | (ly << 16);
}

// ---------------- 5: key squared norms ----------------
__global__ void prepKsq_kernel(const float* __restrict__ f2){
    const int r = blockIdx.x, t = threadIdx.x;
    float2 k = reinterpret_cast<const float2*>(f2 + (long long)r * D)[t];
    float ks = k.x*k.x + k.y*k.y;
    #pragma unroll
    for (int o = 16; o; o >>= 1) ks += __shfl_xor_sync(0xffffffffu, ks, o);
    __shared__ float sw[4];
    if ((t & 31) == 0) sw[t >> 5] = ks;
    __syncthreads();
    if (t == 0) g_ksq[r] = sw[0] + sw[1] + sw[2] + sw[3];
}

// ---------------- main HMMA flash kernel ----------------
// 128 CTAs: qb = bid>>1 (rows qb*128..+128), split = bid&1 (keys split*4096..+4096)
// 128 threads = 4 warps, warp grid 2x2 over (128 rows x 64 keys); warp tile 64x32.
__device__ __forceinline__ void mma_pass(uint32_t abase, uint32_t bbase, float acc[4][4][4]){
    #pragma unroll 4
    for (int kt = 0; kt < 16; kt++){
        uint32_t A[4][4];
        #pragma unroll
        for (int mt = 0; mt < 4; mt++)
            ldm_x4(A[mt][0], A[mt][1], A[mt][2], A[mt][3],
                   abase + (uint32_t)(mt*16*528) + (uint32_t)(kt*32));
        uint32_t B0[4], B1[4];
        ldm_x4(B0[0], B0[1], B0[2], B0[3], bbase + (uint32_t)(kt*32));
        ldm_x4(B1[0], B1[1], B1[2], B1[3], bbase + (uint32_t)(16*528) + (uint32_t)(kt*32));
        #pragma unroll
        for (int mt = 0; mt < 4; mt++){
            mma_bf16(acc[mt][0], A[mt], B0[0], B0[2]);
            mma_bf16(acc[mt][1], A[mt], B0[1], B0[3]);
            mma_bf16(acc[mt][2], A[mt], B1[0], B1[2]);
            mma_bf16(acc[mt][3], A[mt], B1[1], B1[3]);
        }
    }
}

__global__ void __launch_bounds__(128, 1) nce_main_kernel(){
    extern __shared__ __align__(16) uint8_t sm[];
    const uint32_t sb = smem_u32(sm);
    const int tid = threadIdx.x;
    const int lane = tid & 31, wid = tid >> 5;
    const int rw = wid >> 1, cw = wid & 1;        // row-warp, col-warp
    const int g = lane >> 2, t = lane & 3;
    const int bid = blockIdx.x, qb = bid >> 1, split = bid & 1;
    const int m0 = qb * 128;
    const int kbase0 = split * 4096;

    // ---- prologue: Q tiles + chunk-0 K via cp.async ----
    for (int j = tid; j < 128*32; j += 128){
        int row = j >> 5, c = j & 31;
        cpa16(sb + OFF_QH + (uint32_t)(row*528 + c*16), &g_Qhi[(size_t)(m0+row)*128 + c*4]);
        cpa16(sb + OFF_QL + (uint32_t)(row*528 + c*16), &g_Qlo[(size_t)(m0+row)*128 + c*4]);
    }
    for (int j = tid; j < 64*32; j += 128){
        int row = j >> 5, c = j & 31;
        cpa16(sb + OFF_KH + (uint32_t)(row*528 + c*16), &g_Khi[(size_t)(kbase0+row)*128 + c*4]);
        cpa16(sb + OFF_KL + (uint32_t)(row*528 + c*16), &g_Klo[(size_t)(kbase0+row)*128 + c*4]);
    }
    if (tid < 16) cpa16(sb + OFF_KSQ + (uint32_t)(tid*16), &g_ksq[kbase0 + tid*4]);
    CP_COMMIT; CP_WAIT0;
    __syncthreads();

    float qs[4][2];
    #pragma unroll
    for (int mt = 0; mt < 4; mt++){
        qs[mt][0] = g_qsq[m0 + rw*64 + mt*16 + g];
        qs[mt][1] = g_qsq[m0 + rw*64 + mt*16 + g + 8];
    }

    const uint32_t a_off = (uint32_t)((rw*64 + (lane & 15))*528 + (lane >> 4)*16);
    const uint32_t b_off = (uint32_t)((cw*32 + (lane & 15))*528 + (lane >> 4)*16);
    float2* part = (float2*)(sm + OFF_PART);

    float mrun0 = -INFINITY, mrun1 = -INFINITY;
    float srun0 = 0.f, srun1 = 0.f;

    for (int ch = 0; ch < 64; ch++){
        float acc[4][4][4];
        #pragma unroll
        for (int mt = 0; mt < 4; mt++)
            #pragma unroll
            for (int nt = 0; nt < 4; nt++)
                #pragma unroll
                for (int q4 = 0; q4 < 4; q4++) acc[mt][nt][q4] = 0.f;

        // 3-pass split-precision GEMM (hh + lh + hl), same accumulators
        mma_pass(sb + OFF_QH + a_off, sb + OFF_KH + b_off, acc);
        mma_pass(sb + OFF_QL + a_off, sb + OFF_KH + b_off, acc);
        mma_pass(sb + OFF_QH + a_off, sb + OFF_KL + b_off, acc);

        __syncthreads();   // all warps done reading K tile

        if (ch < 63){      // prefetch next chunk; hides under epilogue
            const int bk = kbase0 + (ch + 1)*64;
            for (int j = tid; j < 64*32; j += 128){
                int row = j >> 5, c = j & 31;
                cpa16(sb + OFF_KH + (uint32_t)(row*528 + c*16), &g_Khi[(size_t)(bk+row)*128 + c*4]);
                cpa16(sb + OFF_KL + (uint32_t)(row*528 + c*16), &g_Klo[(size_t)(bk+row)*128 + c*4]);
            }
            if (tid < 16) cpa16(sb + OFF_KSQ + (uint32_t)(((ch+1)&1)*256 + tid*16),
                                &g_ksq[bk + tid*4]);
            CP_COMMIT;
        }

        // ---- epilogue: logits + per-row online logsumexp (log2 domain) ----
        const float* ksq = (const float*)(sm + OFF_KSQ + (ch & 1)*256);
        const int key0 = kbase0 + ch*64;
        #pragma unroll
        for (int mt = 0; mt < 4; mt++){
            #pragma unroll
            for (int h = 0; h < 2; h++){
                const int rloc = rw*64 + mt*16 + g + 8*h;
                float v[8];
                float vmax = -INFINITY;
                #pragma unroll
                for (int nt = 0; nt < 4; nt++){
                    #pragma unroll
                    for (int j = 0; j < 2; j++){
                        const int cl = cw*32 + nt*8 + 2*t + j;
                        float sq = fmaf(acc[mt][nt][h*2 + j], -2.f, qs[mt][h] + ksq[cl]);
                        float lv = -sqrta(fmaxf(sq, 0.f)) * C_L2T;
                        v[nt*2 + j] = lv;
                        vmax = fmaxf(vmax, lv);
                        if (key0 + cl == m0 + rloc) g_pd[m0 + rloc] = lv;
                    }
                }
                vmax = fmaxf(vmax, __shfl_xor_sync(0xffffffffu, vmax, 1));
                vmax = fmaxf(vmax, __shfl_xor_sync(0xffffffffu, vmax, 2));
                float s = 0.f;
                #pragma unroll
                for (int i = 0; i < 8; i++) s += ex2a(v[i] - vmax);
                s += __shfl_xor_sync(0xffffffffu, s, 1);
                s += __shfl_xor_sync(0xffffffffu, s, 2);
                if (t == 0) part[(rw*2 + cw)*64 + mt*16 + g + 8*h] = make_float2(vmax, s);
            }
        }
        __syncthreads();   // partials visible

        if (cw == 0){
            #pragma unroll
            for (int i = 0; i < 2; i++){
                const int rb = lane + i*32;
                float2 p0 = part[(rw*2 + 0)*64 + rb];
                float2 p1 = part[(rw*2 + 1)*64 + rb];
                float mc = fmaxf(p0.x, p1.x);
                float sc = p0.y * ex2a(p0.x - mc) + p1.y * ex2a(p1.x - mc);
                float mr = i ? mrun1 : mrun0;
                float sr = i ? srun1 : srun0;
                float nm = fmaxf(mr, mc);
                sr = sr * ex2a(fmaxf(mr - nm, -126.f)) + sc * ex2a(mc - nm);
                if (i){ mrun1 = nm; srun1 = sr; } else { mrun0 = nm; srun0 = sr; }
            }
        }

        CP_WAIT0;          // next chunk resident
        __syncthreads();   // also guards part[] reuse
    }

    if (cw == 0){
        const int r0 = m0 + rw*64 + lane;
        g_pm[r0*2 + split] = mrun0;  g_ps[r0*2 + split] = srun0;
        const int r1 = r0 + 32;
        g_pm[r1*2 + split] = mrun1;  g_ps[r1*2 + split] = srun1;
    }
}

// ---------------- 7: merge splits + mean ----------------
__global__ void fin_kernel(float* __restrict__ out){
    float acc = 0.f;
    for (int r = threadIdx.x; r < P; r += 256){
        float ma = g_pm[2*r], mb = g_pm[2*r + 1];
        float sa = g_ps[2*r], sb = g_ps[2*r + 1];
        float m = fmaxf(ma, mb);
        float s = sa * ex2a(fmaxf(ma - m, -126.f)) + sb * ex2a(fmaxf(mb - m, -126.f));
        acc += LN2F * (m + __log2f(s) - g_pd[r]);
    }
    #pragma unroll
    for (int o = 16; o; o >>= 1) acc += __shfl_xor_sync(0xffffffffu, acc, o);
    __shared__ float sw[8];
    if ((threadIdx.x & 31) == 0) sw[threadIdx.x >> 5] = acc;
    __syncthreads();
    if (threadIdx.x == 0){
        float tt = 0.f;
        #pragma unroll
        for (int i = 0; i < 8; i++) tt += sw[i];
        out[0] = tt / (float)P;
    }
}

extern "C" void kernel_launch(void* const* d_in, const int* in_sizes, int n_in,
                              void* d_out, int out_size){
    const float* f1  = (const float*)d_in[0];
    const float* f2  = (const float*)d_in[1];
    const void*  map = d_in[2];

    cudaFuncSetAttribute(nce_main_kernel,
                         cudaFuncAttributeMaxDynamicSharedMemorySize, SMEM_TOTAL);

    detect_kernel<<<1, 256>>>((const int*)map);        // launch 1
    prepQ_kernel<<<P, 128>>>(f1, map);                 // launch 2
    prepKhi_kernel<<<P, 128>>>(f2);                    // launch 3
    prepKlo_kernel<<<P, 128>>>(f2);                    // launch 4
    prepKsq_kernel<<<P, 128>>>(f2);                    // launch 5
    nce_main_kernel<<<128, 128, SMEM_TOTAL>>>();       // launch 6 (ncu -s 5 -c 1 target)
    fin_kernel<<<1, 256>>>((float*)d_out);             // launch 7
}

// round 4
// speedup vs baseline: 6.2369x; 2.3228x over previous
#include <cuda_runtime.h>
#include <cuda_bf16.h>
#include <stdint.h>
#include <math.h>

#define P 8192
#define D 256
#define C_L2T 20.60992915555662f   // log2(e)/0.07
#define LN2F  0.6931471805599453f

// ---------------- device scratch (allocation-free) ----------------
__device__ int g_is64;
__device__ __align__(16) uint32_t g_Qh[P * 128];   // bf16x2 packed, row-major [row][128]
__device__ __align__(16) uint32_t g_Kh[P * 128];
__device__ float g_qsq[P];
__device__ float g_ksq[P];
__device__ float g_pm[P * 2];
__device__ float g_ps[P * 2];
__device__ float g_pd[P];

// ---------------- smem layout (bytes) ----------------
// rows stride 528B (264 bf16): 528 % 128 == 16 -> ldmatrix conflict-free phasing
#define OFF_QH   0               // 128*528 = 67584
#define OFF_K0   67584           // 64*528  = 33792
#define OFF_K1   101376
#define OFF_KSQ  135168          // 2 bufs x 256B
#define OFF_PART 135680          // float2[4][2][32] = 2048B
#define SMEM_TOTAL 137728

// ---------------- PTX helpers (base-PTX only, sm_103-safe) ----------------
__device__ __forceinline__ uint32_t smem_u32(const void* p){
    uint32_t a;
    asm("{ .reg .u64 t; cvta.to.shared.u64 t, %1; cvt.u32.u64 %0, t; }" : "=r"(a) : "l"(p));
    return a;
}
__device__ __forceinline__ void cpa16(uint32_t dst, const void* src){
    asm volatile("cp.async.cg.shared.global [%0], [%1], 16;" :: "r"(dst), "l"(src));
}
#define CP_COMMIT asm volatile("cp.async.commit_group;" ::: "memory")
#define CP_WAIT0  asm volatile("cp.async.wait_group 0;" ::: "memory")

__device__ __forceinline__ void ldm_x4(uint32_t& r0, uint32_t& r1, uint32_t& r2, uint32_t& r3,
                                       uint32_t addr){
    asm volatile("ldmatrix.sync.aligned.m8n8.x4.shared.b16 {%0,%1,%2,%3}, [%4];"
                 : "=r"(r0), "=r"(r1), "=r"(r2), "=r"(r3) : "r"(addr));
}
__device__ __forceinline__ void mma_bf16(float c[4], const uint32_t a[4],
                                         uint32_t b0, uint32_t b1){
    asm volatile(
        "mma.sync.aligned.m16n8k16.row.col.f32.bf16.bf16.f32 "
        "{%0,%1,%2,%3}, {%4,%5,%6,%7}, {%8,%9}, {%0,%1,%2,%3};"
        : "+f"(c[0]), "+f"(c[1]), "+f"(c[2]), "+f"(c[3])
        : "r"(a[0]), "r"(a[1]), "r"(a[2]), "r"(a[3]), "r"(b0), "r"(b1));
}
__device__ __forceinline__ float ex2a(float x){ float y; asm("ex2.approx.f32 %0, %1;" : "=f"(y) : "f"(x)); return y; }
__device__ __forceinline__ float sqrta(float x){ float y; asm("sqrt.approx.f32 %0, %1;" : "=f"(y) : "f"(x)); return y; }
__device__ __forceinline__ uint32_t f2bf_bits(float x){
    return (uint32_t)__bfloat16_as_ushort(__float2bfloat16(x));
}

// ---------------- 1: dtype detection (int64 vs int32 map) ----------------
__global__ void detect_kernel(const int* __restrict__ m32){
    __shared__ int nz;
    if (threadIdx.x == 0) nz = 0;
    __syncthreads();
    int any = 0;
    for (int i = 1 + 2*(int)threadIdx.x; i < P; i += 2*(int)blockDim.x)
        if (m32[i] != 0) any = 1;
    if (any) atomicOr(&nz, 1);
    __syncthreads();
    if (threadIdx.x == 0) g_is64 = (nz == 0) ? 1 : 0;
}

// ---------------- 2: gather Q -> bf16 pack + qsq ----------------
__global__ void prepQ_kernel(const float* __restrict__ f1, const void* __restrict__ map){
    const int r = blockIdx.x, t = threadIdx.x;
    long long idx = g_is64 ? ((const long long*)map)[r]
                           : (long long)((const int*)map)[r];
    float2 q = reinterpret_cast<const float2*>(f1 + idx * (long long)D)[t];
    g_Qh[r*128 + t] = f2bf_bits(q.x) | (f2bf_bits(q.y) << 16);
    float qs = q.x*q.x + q.y*q.y;
    #pragma unroll
    for (int o = 16; o; o >>= 1) qs += __shfl_xor_sync(0xffffffffu, qs, o);
    __shared__ float sw[4];
    if ((t & 31) == 0) sw[t >> 5] = qs;
    __syncthreads();
    if (t == 0) g_qsq[r] = sw[0] + sw[1] + sw[2] + sw[3];
}

// ---------------- 3: K -> bf16 pack + ksq (fused) ----------------
__global__ void prepK_kernel(const float* __restrict__ f2){
    const int r = blockIdx.x, t = threadIdx.x;
    float2 k = reinterpret_cast<const float2*>(f2 + (long long)r * D)[t];
    g_Kh[r*128 + t] = f2bf_bits(k.x) | (f2bf_bits(k.y) << 16);
    float ks = k.x*k.x + k.y*k.y;
    #pragma unroll
    for (int o = 16; o; o >>= 1) ks += __shfl_xor_sync(0xffffffffu, ks, o);
    __shared__ float sw[4];
    if ((t & 31) == 0) sw[t >> 5] = ks;
    __syncthreads();
    if (t == 0) g_ksq[r] = sw[0] + sw[1] + sw[2] + sw[3];
}

// ---------------- 4: main HMMA flash kernel ----------------
// 128 CTAs: qb = bid>>1 (rows qb*128..+128), split = bid&1 (keys split*4096..+4096)
// 256 threads = 8 warps: 4 row-warps x 2 col-warps, warp tile 32 rows x 32 keys.
// Single bf16 pass (exact fp32 norms); K chunk (64 keys) double-buffered,
// prefetch issued BEFORE the MMA so it overlaps compute.
__global__ void __launch_bounds__(256, 1) nce_main_kernel(){
    extern __shared__ __align__(16) uint8_t sm[];
    const uint32_t sb = smem_u32(sm);
    const int tid = threadIdx.x;
    const int lane = tid & 31, wid = tid >> 5;
    const int rw = wid >> 1, cw = wid & 1;      // row-warp (0..3), col-warp (0..1)
    const int g = lane >> 2, t = lane & 3;
    const int bid = blockIdx.x, qb = bid >> 1, split = bid & 1;
    const int m0 = qb * 128;
    const int kbase0 = split * 4096;

    // ---- prologue: Q tile + chunk-0 K via cp.async ----
    for (int j = tid; j < 128*32; j += 256){
        int row = j >> 5, c = j & 31;
        cpa16(sb + OFF_QH + (uint32_t)(row*528 + c*16), &g_Qh[(size_t)(m0+row)*128 + c*4]);
    }
    for (int j = tid; j < 64*32; j += 256){
        int row = j >> 5, c = j & 31;
        cpa16(sb + OFF_K0 + (uint32_t)(row*528 + c*16), &g_Kh[(size_t)(kbase0+row)*128 + c*4]);
    }
    if (tid < 16) cpa16(sb + OFF_KSQ + (uint32_t)(tid*16), &g_ksq[kbase0 + tid*4]);
    CP_COMMIT; CP_WAIT0;
    __syncthreads();

    float qs[2][2];
    #pragma unroll
    for (int mt = 0; mt < 2; mt++){
        qs[mt][0] = g_qsq[m0 + rw*32 + mt*16 + g];
        qs[mt][1] = g_qsq[m0 + rw*32 + mt*16 + g + 8];
    }

    const uint32_t a_off = sb + OFF_QH + (uint32_t)((rw*32 + (lane & 15))*528 + (lane >> 4)*16);
    const uint32_t b_off = (uint32_t)((cw*32 + (lane & 15))*528 + (lane >> 4)*16);
    float2* part = (float2*)(sm + OFF_PART);

    float mrun = -INFINITY, srun = 0.f;

    for (int ch = 0; ch < 64; ch++){
        const int buf = ch & 1;

        // prefetch next chunk into the other buffer (overlaps MMA + epilogue)
        if (ch < 63){
            const int bk = kbase0 + (ch + 1)*64;
            const uint32_t kdst = sb + (buf ? OFF_K0 : OFF_K1);
            for (int j = tid; j < 64*32; j += 256){
                int row = j >> 5, c = j & 31;
                cpa16(kdst + (uint32_t)(row*528 + c*16), &g_Kh[(size_t)(bk+row)*128 + c*4]);
            }
            if (tid < 16) cpa16(sb + OFF_KSQ + (uint32_t)((buf^1)*256 + tid*16),
                                &g_ksq[bk + tid*4]);
            CP_COMMIT;
        }

        // ---- single-pass bf16 MMA on current buffer ----
        float acc[2][4][4];
        #pragma unroll
        for (int mt = 0; mt < 2; mt++)
            #pragma unroll
            for (int nt = 0; nt < 4; nt++)
                #pragma unroll
                for (int q4 = 0; q4 < 4; q4++) acc[mt][nt][q4] = 0.f;

        const uint32_t bbase = sb + (buf ? OFF_K1 : OFF_K0) + b_off;
        #pragma unroll
        for (int kt = 0; kt < 16; kt++){
            uint32_t A[2][4];
            #pragma unroll
            for (int mt = 0; mt < 2; mt++)
                ldm_x4(A[mt][0], A[mt][1], A[mt][2], A[mt][3],
                       a_off + (uint32_t)(mt*16*528) + (uint32_t)(kt*32));
            uint32_t B0[4], B1[4];
            ldm_x4(B0[0], B0[1], B0[2], B0[3], bbase + (uint32_t)(kt*32));
            ldm_x4(B1[0], B1[1], B1[2], B1[3], bbase + (uint32_t)(16*528) + (uint32_t)(kt*32));
            #pragma unroll
            for (int mt = 0; mt < 2; mt++){
                mma_bf16(acc[mt][0], A[mt], B0[0], B0[2]);
                mma_bf16(acc[mt][1], A[mt], B0[1], B0[3]);
                mma_bf16(acc[mt][2], A[mt], B1[0], B1[2]);
                mma_bf16(acc[mt][3], A[mt], B1[1], B1[3]);
            }
        }

        // ---- epilogue: logits + per-row online logsumexp (log2 domain) ----
        const float* ksq = (const float*)(sm + OFF_KSQ + buf*256);
        const int key0 = kbase0 + ch*64;
        #pragma unroll
        for (int mt = 0; mt < 2; mt++){
            #pragma unroll
            for (int h = 0; h < 2; h++){
                const int rloc = rw*32 + mt*16 + g + 8*h;
                float v[8];
                float vmax = -INFINITY;
                #pragma unroll
                for (int nt = 0; nt < 4; nt++){
                    #pragma unroll
                    for (int j = 0; j < 2; j++){
                        const int cl = cw*32 + nt*8 + 2*t + j;
                        float sq = fmaf(acc[mt][nt][h*2 + j], -2.f, qs[mt][h] + ksq[cl]);
                        float lv = -sqrta(fmaxf(sq, 0.f)) * C_L2T;
                        v[nt*2 + j] = lv;
                        vmax = fmaxf(vmax, lv);
                        if (key0 + cl == m0 + rloc) g_pd[m0 + rloc] = lv;
                    }
                }
                vmax = fmaxf(vmax, __shfl_xor_sync(0xffffffffu, vmax, 1));
                vmax = fmaxf(vmax, __shfl_xor_sync(0xffffffffu, vmax, 2));
                float s = 0.f;
                #pragma unroll
                for (int i = 0; i < 8; i++) s += ex2a(v[i] - vmax);
                s += __shfl_xor_sync(0xffffffffu, s, 1);
                s += __shfl_xor_sync(0xffffffffu, s, 2);
                if (t == 0) part[(rw*2 + cw)*32 + rloc - rw*32] = make_float2(vmax, s);
            }
        }
        __syncthreads();   // partials visible

        if (cw == 0){
            float2 p0 = part[(rw*2 + 0)*32 + lane];
            float2 p1 = part[(rw*2 + 1)*32 + lane];
            float mc = fmaxf(p0.x, p1.x);
            float sc = p0.y * ex2a(p0.x - mc) + p1.y * ex2a(p1.x - mc);
            float nm = fmaxf(mrun, mc);
            srun = srun * ex2a(fmaxf(mrun - nm, -126.f)) + sc * ex2a(mc - nm);
            mrun = nm;
        }

        CP_WAIT0;          // next chunk resident
        __syncthreads();   // guards part[] reuse + K buffer rotation
    }

    if (cw == 0){
        const int row = m0 + rw*32 + lane;
        g_pm[row*2 + split] = mrun;
        g_ps[row*2 + split] = srun;
    }
}

// ---------------- 5: merge splits + mean ----------------
__global__ void fin_kernel(float* __restrict__ out){
    float acc = 0.f;
    for (int r = threadIdx.x; r < P; r += 256){
        float ma = g_pm[2*r], mb = g_pm[2*r + 1];
        float sa = g_ps[2*r], sb = g_ps[2*r + 1];
        float m = fmaxf(ma, mb);
        float s = sa * ex2a(fmaxf(ma - m, -126.f)) + sb * ex2a(fmaxf(mb - m, -126.f));
        acc += LN2F * (m + __log2f(s) - g_pd[r]);
    }
    #pragma unroll
    for (int o = 16; o; o >>= 1) acc += __shfl_xor_sync(0xffffffffu, acc, o);
    __shared__ float sw[8];
    if ((threadIdx.x & 31) == 0) sw[threadIdx.x >> 5] = acc;
    __syncthreads();
    if (threadIdx.x == 0){
        float tt = 0.f;
        #pragma unroll
        for (int i = 0; i < 8; i++) tt += sw[i];
        out[0] = tt / (float)P;
    }
}

extern "C" void kernel_launch(void* const* d_in, const int* in_sizes, int n_in,
                              void* d_out, int out_size){
    const float* f1  = (const float*)d_in[0];
    const float* f2  = (const float*)d_in[1];
    const void*  map = d_in[2];

    cudaFuncSetAttribute(nce_main_kernel,
                         cudaFuncAttributeMaxDynamicSharedMemorySize, SMEM_TOTAL);

    detect_kernel<<<1, 256>>>((const int*)map);    // launch 1
    prepQ_kernel<<<P, 128>>>(f1, map);             // launch 2
    prepK_kernel<<<P, 128>>>(f2);                  // launch 3
    nce_main_kernel<<<128, 256, SMEM_TOTAL>>>();   // launch 4 (ncu profiles #4 empirically)
    fin_kernel<<<1, 256>>>((float*)d_out);         // launch 5
}

// round 5
// speedup vs baseline: 6.8271x; 1.0946x over previous
#include <cuda_runtime.h>
#include <cuda_bf16.h>
#include <stdint.h>
#include <math.h>

#define P 8192
#define D 256
#define C_L2T 20.60992915555662f   // log2(e)/0.07
#define LN2F  0.6931471805599453f

// ---------------- device scratch (allocation-free) ----------------
__device__ int g_is64;
__device__ __align__(16) uint32_t g_Qh[P * 128];   // bf16x2 packed, row-major [row][128]
__device__ __align__(16) uint32_t g_Kh[P * 128];
__device__ float g_qsq[P];
__device__ float g_ksq[P];
__device__ float g_pm[P * 2];
__device__ float g_ps[P * 2];
__device__ float g_pd[P];

// ---------------- smem layout (bytes) ----------------
// rows stride 528B (264 bf16): 8-row ldmatrix groups land on distinct 16B banks
#define OFF_QH   0               // 128*528 = 67584
#define OFF_K0   67584           // 128*528
#define OFF_K1   135168          // 128*528
#define OFF_KSQ  202752          // 2 bufs x 512B
#define OFF_PART 203776          // float2[16][32] = 4096B
#define SMEM_TOTAL 207872

// ---------------- PTX helpers (base-PTX only, sm_103-safe) ----------------
__device__ __forceinline__ uint32_t smem_u32(const void* p){
    uint32_t a;
    asm("{ .reg .u64 t; cvta.to.shared.u64 t, %1; cvt.u32.u64 %0, t; }" : "=r"(a) : "l"(p));
    return a;
}
__device__ __forceinline__ void cpa16(uint32_t dst, const void* src){
    asm volatile("cp.async.cg.shared.global [%0], [%1], 16;" :: "r"(dst), "l"(src));
}
#define CP_COMMIT asm volatile("cp.async.commit_group;" ::: "memory")
#define CP_WAIT0  asm volatile("cp.async.wait_group 0;" ::: "memory")

__device__ __forceinline__ void ldm_x4(uint32_t& r0, uint32_t& r1, uint32_t& r2, uint32_t& r3,
                                       uint32_t addr){
    asm volatile("ldmatrix.sync.aligned.m8n8.x4.shared.b16 {%0,%1,%2,%3}, [%4];"
                 : "=r"(r0), "=r"(r1), "=r"(r2), "=r"(r3) : "r"(addr));
}
__device__ __forceinline__ void mma_bf16(float c[4], const uint32_t a[4],
                                         uint32_t b0, uint32_t b1){
    asm volatile(
        "mma.sync.aligned.m16n8k16.row.col.f32.bf16.bf16.f32 "
        "{%0,%1,%2,%3}, {%4,%5,%6,%7}, {%8,%9}, {%0,%1,%2,%3};"
        : "+f"(c[0]), "+f"(c[1]), "+f"(c[2]), "+f"(c[3])
        : "r"(a[0]), "r"(a[1]), "r"(a[2]), "r"(a[3]), "r"(b0), "r"(b1));
}
__device__ __forceinline__ float ex2a(float x){ float y; asm("ex2.approx.f32 %0, %1;" : "=f"(y) : "f"(x)); return y; }
__device__ __forceinline__ float sqrta(float x){ float y; asm("sqrt.approx.f32 %0, %1;" : "=f"(y) : "f"(x)); return y; }
__device__ __forceinline__ uint32_t f2bf_bits(float x){
    return (uint32_t)__bfloat16_as_ushort(__float2bfloat16(x));
}

// ---------------- 1: dtype detection (int64 vs int32 map) ----------------
__global__ void detect_kernel(const int* __restrict__ m32){
    __shared__ int nz;
    if (threadIdx.x == 0) nz = 0;
    __syncthreads();
    int any = 0;
    for (int i = 1 + 2*(int)threadIdx.x; i < P; i += 2*(int)blockDim.x)
        if (m32[i] != 0) any = 1;
    if (any) atomicOr(&nz, 1);
    __syncthreads();
    if (threadIdx.x == 0) g_is64 = (nz == 0) ? 1 : 0;
}

// ---------------- 2: gather Q -> bf16 pack + qsq ----------------
__global__ void prepQ_kernel(const float* __restrict__ f1, const void* __restrict__ map){
    const int r = blockIdx.x, t = threadIdx.x;
    long long idx = g_is64 ? ((const long long*)map)[r]
                           : (long long)((const int*)map)[r];
    float2 q = reinterpret_cast<const float2*>(f1 + idx * (long long)D)[t];
    g_Qh[r*128 + t] = f2bf_bits(q.x) | (f2bf_bits(q.y) << 16);
    float qs = q.x*q.x + q.y*q.y;
    #pragma unroll
    for (int o = 16; o; o >>= 1) qs += __shfl_xor_sync(0xffffffffu, qs, o);
    __shared__ float sw[4];
    if ((t & 31) == 0) sw[t >> 5] = qs;
    __syncthreads();
    if (t == 0) g_qsq[r] = sw[0] + sw[1] + sw[2] + sw[3];
}

// ---------------- 3: K -> bf16 pack + ksq (fused) ----------------
__global__ void prepK_kernel(const float* __restrict__ f2){
    const int r = blockIdx.x, t = threadIdx.x;
    float2 k = reinterpret_cast<const float2*>(f2 + (long long)r * D)[t];
    g_Kh[r*128 + t] = f2bf_bits(k.x) | (f2bf_bits(k.y) << 16);
    float ks = k.x*k.x + k.y*k.y;
    #pragma unroll
    for (int o = 16; o; o >>= 1) ks += __shfl_xor_sync(0xffffffffu, ks, o);
    __shared__ float sw[4];
    if ((t & 31) == 0) sw[t >> 5] = ks;
    __syncthreads();
    if (t == 0) g_ksq[r] = sw[0] + sw[1] + sw[2] + sw[3];
}

// ---------------- 4: main HMMA flash kernel ----------------
// 128 CTAs: qb = bid>>1 (rows qb*128..+128), split = bid&1 (keys split*4096..+4096)
// 512 threads = 16 warps: 4 row-warps x 4 col-warps; warp tile 32 rows x 32 keys.
// K chunk = 128 keys, double-buffered; prefetch issued BEFORE the MMA.
__global__ void __launch_bounds__(512, 1) nce_main_kernel(){
    extern __shared__ __align__(16) uint8_t sm[];
    const uint32_t sb = smem_u32(sm);
    const int tid = threadIdx.x;
    const int lane = tid & 31, wid = tid >> 5;
    const int rw = wid >> 2, cw = wid & 3;      // row-warp (0..3), col-warp (0..3)
    const int g = lane >> 2, t = lane & 3;
    const int bid = blockIdx.x, qb = bid >> 1, split = bid & 1;
    const int m0 = qb << 7;
    const int kbase0 = split * 4096;
    // the single 128-key chunk containing this CTA's diagonals (or -1)
    const int diag_ch = ((qb >> 5) == split) ? (qb & 31) : -1;

    // ---- prologue: Q tile + chunk-0 K via cp.async ----
    for (int j = tid; j < 128*32; j += 512){
        int row = j >> 5, c = j & 31;
        cpa16(sb + OFF_QH + (uint32_t)(row*528 + c*16), &g_Qh[(size_t)(m0+row)*128 + c*4]);
        cpa16(sb + OFF_K0 + (uint32_t)(row*528 + c*16), &g_Kh[(size_t)(kbase0+row)*128 + c*4]);
    }
    if (tid < 32) cpa16(sb + OFF_KSQ + (uint32_t)(tid*16), &g_ksq[kbase0 + tid*4]);
    CP_COMMIT; CP_WAIT0;
    __syncthreads();

    float qs[2][2];
    #pragma unroll
    for (int mt = 0; mt < 2; mt++){
        qs[mt][0] = g_qsq[m0 + rw*32 + mt*16 + g];
        qs[mt][1] = g_qsq[m0 + rw*32 + mt*16 + g + 8];
    }

    const uint32_t a_off = sb + OFF_QH + (uint32_t)((rw*32 + (lane & 15))*528 + (lane >> 4)*16);
    const uint32_t b_off = (uint32_t)((cw*32 + (lane & 15))*528 + (lane >> 4)*16);
    float2* part = (float2*)(sm + OFF_PART);

    float mrun = -INFINITY, srun = 0.f;

    for (int ch = 0; ch < 32; ch++){
        const int buf = ch & 1;

        // prefetch next 128-key chunk into the other buffer (overlaps MMA+epilogue)
        if (ch < 31){
            const int bk = kbase0 + (ch + 1)*128;
            const uint32_t kdst = sb + (buf ? OFF_K0 : OFF_K1);
            for (int j = tid; j < 128*32; j += 512){
                int row = j >> 5, c = j & 31;
                cpa16(kdst + (uint32_t)(row*528 + c*16), &g_Kh[(size_t)(bk+row)*128 + c*4]);
            }
            if (tid < 32) cpa16(sb + OFF_KSQ + (uint32_t)((buf^1)*512 + tid*16),
                                &g_ksq[bk + tid*4]);
            CP_COMMIT;
        }

        // ---- single-pass bf16 MMA on current buffer ----
        float acc[2][4][4];
        #pragma unroll
        for (int mt = 0; mt < 2; mt++)
            #pragma unroll
            for (int nt = 0; nt < 4; nt++)
                #pragma unroll
                for (int q4 = 0; q4 < 4; q4++) acc[mt][nt][q4] = 0.f;

        const uint32_t bbase = sb + (buf ? OFF_K1 : OFF_K0) + b_off;
        #pragma unroll 4
        for (int kt = 0; kt < 16; kt++){
            uint32_t A[2][4];
            #pragma unroll
            for (int mt = 0; mt < 2; mt++)
                ldm_x4(A[mt][0], A[mt][1], A[mt][2], A[mt][3],
                       a_off + (uint32_t)(mt*16*528) + (uint32_t)(kt*32));
            uint32_t B0[4], B1[4];
            ldm_x4(B0[0], B0[1], B0[2], B0[3], bbase + (uint32_t)(kt*32));
            ldm_x4(B1[0], B1[1], B1[2], B1[3], bbase + (uint32_t)(16*528) + (uint32_t)(kt*32));
            #pragma unroll
            for (int mt = 0; mt < 2; mt++){
                mma_bf16(acc[mt][0], A[mt], B0[0], B0[2]);
                mma_bf16(acc[mt][1], A[mt], B0[1], B0[3]);
                mma_bf16(acc[mt][2], A[mt], B1[0], B1[2]);
                mma_bf16(acc[mt][3], A[mt], B1[1], B1[3]);
            }
        }

        // ---- epilogue: logits + per-row online logsumexp (log2 domain) ----
        const float* ksq = (const float*)(sm + OFF_KSQ + buf*512);
        float kq[8];
        #pragma unroll
        for (int nt = 0; nt < 4; nt++){
            kq[nt*2]   = ksq[cw*32 + nt*8 + 2*t];
            kq[nt*2+1] = ksq[cw*32 + nt*8 + 2*t + 1];
        }
        const bool has_diag = (ch == diag_ch);
        #pragma unroll
        for (int mt = 0; mt < 2; mt++){
            #pragma unroll
            for (int h = 0; h < 2; h++){
                const int rloc = rw*32 + mt*16 + g + 8*h;
                float v[8];
                float vmax = -INFINITY;
                #pragma unroll
                for (int nt = 0; nt < 4; nt++){
                    #pragma unroll
                    for (int j = 0; j < 2; j++){
                        float sq = fmaf(acc[mt][nt][h*2 + j], -2.f, qs[mt][h] + kq[nt*2 + j]);
                        float lv = -sqrta(fmaxf(sq, 0.f)) * C_L2T;
                        v[nt*2 + j] = lv;
                        vmax = fmaxf(vmax, lv);
                    }
                }
                if (has_diag){   // diag key local col == rloc, 1 chunk in 32
                    #pragma unroll
                    for (int nt = 0; nt < 4; nt++)
                        #pragma unroll
                        for (int j = 0; j < 2; j++)
                            if (cw*32 + nt*8 + 2*t + j == rloc) g_pd[m0 + rloc] = v[nt*2 + j];
                }
                vmax = fmaxf(vmax, __shfl_xor_sync(0xffffffffu, vmax, 1));
                vmax = fmaxf(vmax, __shfl_xor_sync(0xffffffffu, vmax, 2));
                float s = 0.f;
                #pragma unroll
                for (int i = 0; i < 8; i++) s += ex2a(v[i] - vmax);
                s += __shfl_xor_sync(0xffffffffu, s, 1);
                s += __shfl_xor_sync(0xffffffffu, s, 2);
                if (t == 0) part[(rw*4 + cw)*32 + mt*16 + g + 8*h] = make_float2(vmax, s);
            }
        }
        __syncthreads();   // partials visible

        if (cw == 0){
            float2 p0 = part[(rw*4 + 0)*32 + lane];
            float2 p1 = part[(rw*4 + 1)*32 + lane];
            float2 p2 = part[(rw*4 + 2)*32 + lane];
            float2 p3 = part[(rw*4 + 3)*32 + lane];
            float mc = fmaxf(fmaxf(p0.x, p1.x), fmaxf(p2.x, p3.x));
            float sc = p0.y * ex2a(p0.x - mc) + p1.y * ex2a(p1.x - mc)
                     + p2.y * ex2a(p2.x - mc) + p3.y * ex2a(p3.x - mc);
            float nm = fmaxf(mrun, mc);
            srun = srun * ex2a(fmaxf(mrun - nm, -126.f)) + sc * ex2a(mc - nm);
            mrun = nm;
        }

        CP_WAIT0;          // next chunk resident
        __syncthreads();   // guards part[] reuse + K buffer rotation
    }

    if (cw == 0){
        const int row = m0 + rw*32 + lane;
        g_pm[row*2 + split] = mrun;
        g_ps[row*2 + split] = srun;
    }
}

// ---------------- 5: merge splits + mean ----------------
__global__ void fin_kernel(float* __restrict__ out){
    float acc = 0.f;
    for (int r = threadIdx.x; r < P; r += 256){
        float ma = g_pm[2*r], mb = g_pm[2*r + 1];
        float sa = g_ps[2*r], sb = g_ps[2*r + 1];
        float m = fmaxf(ma, mb);
        float s = sa * ex2a(fmaxf(ma - m, -126.f)) + sb * ex2a(fmaxf(mb - m, -126.f));
        acc += LN2F * (m + __log2f(s) - g_pd[r]);
    }
    #pragma unroll
    for (int o = 16; o; o >>= 1) acc += __shfl_xor_sync(0xffffffffu, acc, o);
    __shared__ float sw[8];
    if ((threadIdx.x & 31) == 0) sw[threadIdx.x >> 5] = acc;
    __syncthreads();
    if (threadIdx.x == 0){
        float tt = 0.f;
        #pragma unroll
        for (int i = 0; i < 8; i++) tt += sw[i];
        out[0] = tt / (float)P;
    }
}

extern "C" void kernel_launch(void* const* d_in, const int* in_sizes, int n_in,
                              void* d_out, int out_size){
    const float* f1  = (const float*)d_in[0];
    const float* f2  = (const float*)d_in[1];
    const void*  map = d_in[2];

    cudaFuncSetAttribute(nce_main_kernel,
                         cudaFuncAttributeMaxDynamicSharedMemorySize, SMEM_TOTAL);

    detect_kernel<<<1, 256>>>((const int*)map);    // launch 1
    prepQ_kernel<<<P, 128>>>(f1, map);             // launch 2
    prepK_kernel<<<P, 128>>>(f2);                  // launch 3
    nce_main_kernel<<<128, 512, SMEM_TOTAL>>>();   // launch 4 (ncu target)
    fin_kernel<<<1, 256>>>((float*)d_out);         // launch 5
}

// round 6
// speedup vs baseline: 6.8889x; 1.0091x over previous
#include <cuda_runtime.h>
#include <cuda_bf16.h>
#include <stdint.h>
#include <math.h>

#define P 8192
#define D 256
#define C_L2T 20.60992915555662f   // log2(e)/0.07
#define LN2F  0.6931471805599453f

// ---------------- device scratch (allocation-free) ----------------
__device__ int g_is64;
__device__ __align__(16) uint32_t g_Qh[P * 128];   // bf16x2 packed, row-major [row][128]
__device__ __align__(16) uint32_t g_Kh[P * 128];
__device__ float g_qsq[P];
__device__ float g_ksq[P];
__device__ float g_pm[P * 2];
__device__ float g_ps[P * 2];
__device__ float g_pd[P];

// ---------------- smem layout (bytes) ----------------
// rows stride 528B (264 bf16): 8-row ldmatrix groups land on distinct 16B banks
#define OFF_QH   0               // 128*528 = 67584
#define OFF_K0   67584           // 128*528
#define OFF_K1   135168          // 128*528
#define OFF_KSQ  202752          // 2 bufs x 512B
#define OFF_PART 203776          // float2[4][128] = 4096B (final combine only)
#define SMEM_TOTAL 207872

// ---------------- PTX helpers (base-PTX only, sm_103-safe) ----------------
__device__ __forceinline__ uint32_t smem_u32(const void* p){
    uint32_t a;
    asm("{ .reg .u64 t; cvta.to.shared.u64 t, %1; cvt.u32.u64 %0, t; }" : "=r"(a) : "l"(p));
    return a;
}
__device__ __forceinline__ void cpa16(uint32_t dst, const void* src){
    asm volatile("cp.async.cg.shared.global [%0], [%1], 16;" :: "r"(dst), "l"(src));
}
#define CP_COMMIT asm volatile("cp.async.commit_group;" ::: "memory")
#define CP_WAIT0  asm volatile("cp.async.wait_group 0;" ::: "memory")

__device__ __forceinline__ void ldm_x4(uint32_t& r0, uint32_t& r1, uint32_t& r2, uint32_t& r3,
                                       uint32_t addr){
    asm volatile("ldmatrix.sync.aligned.m8n8.x4.shared.b16 {%0,%1,%2,%3}, [%4];"
                 : "=r"(r0), "=r"(r1), "=r"(r2), "=r"(r3) : "r"(addr));
}
__device__ __forceinline__ void mma_bf16(float c[4], const uint32_t a[4],
                                         uint32_t b0, uint32_t b1){
    asm volatile(
        "mma.sync.aligned.m16n8k16.row.col.f32.bf16.bf16.f32 "
        "{%0,%1,%2,%3}, {%4,%5,%6,%7}, {%8,%9}, {%0,%1,%2,%3};"
        : "+f"(c[0]), "+f"(c[1]), "+f"(c[2]), "+f"(c[3])
        : "r"(a[0]), "r"(a[1]), "r"(a[2]), "r"(a[3]), "r"(b0), "r"(b1));
}
__device__ __forceinline__ float ex2a(float x){ float y; asm("ex2.approx.f32 %0, %1;" : "=f"(y) : "f"(x)); return y; }
__device__ __forceinline__ float sqrta(float x){ float y; asm("sqrt.approx.f32 %0, %1;" : "=f"(y) : "f"(x)); return y; }
__device__ __forceinline__ uint32_t f2bf_bits(float x){
    return (uint32_t)__bfloat16_as_ushort(__float2bfloat16(x));
}

// ---------------- 1: dtype detection (int64 vs int32 map) ----------------
__global__ void detect_kernel(const int* __restrict__ m32){
    __shared__ int nz;
    if (threadIdx.x == 0) nz = 0;
    __syncthreads();
    int any = 0;
    for (int i = 1 + 2*(int)threadIdx.x; i < P; i += 2*(int)blockDim.x)
        if (m32[i] != 0) any = 1;
    if (any) atomicOr(&nz, 1);
    __syncthreads();
    if (threadIdx.x == 0) g_is64 = (nz == 0) ? 1 : 0;
}

// ---------------- 2: gather Q -> bf16 pack + qsq ----------------
__global__ void prepQ_kernel(const float* __restrict__ f1, const void* __restrict__ map){
    const int r = blockIdx.x, t = threadIdx.x;
    long long idx = g_is64 ? ((const long long*)map)[r]
                           : (long long)((const int*)map)[r];
    float2 q = reinterpret_cast<const float2*>(f1 + idx * (long long)D)[t];
    g_Qh[r*128 + t] = f2bf_bits(q.x) | (f2bf_bits(q.y) << 16);
    float qs = q.x*q.x + q.y*q.y;
    #pragma unroll
    for (int o = 16; o; o >>= 1) qs += __shfl_xor_sync(0xffffffffu, qs, o);
    __shared__ float sw[4];
    if ((t & 31) == 0) sw[t >> 5] = qs;
    __syncthreads();
    if (t == 0) g_qsq[r] = sw[0] + sw[1] + sw[2] + sw[3];
}

// ---------------- 3: K -> bf16 pack + ksq (fused) ----------------
__global__ void prepK_kernel(const float* __restrict__ f2){
    const int r = blockIdx.x, t = threadIdx.x;
    float2 k = reinterpret_cast<const float2*>(f2 + (long long)r * D)[t];
    g_Kh[r*128 + t] = f2bf_bits(k.x) | (f2bf_bits(k.y) << 16);
    float ks = k.x*k.x + k.y*k.y;
    #pragma unroll
    for (int o = 16; o; o >>= 1) ks += __shfl_xor_sync(0xffffffffu, ks, o);
    __shared__ float sw[4];
    if ((t & 31) == 0) sw[t >> 5] = ks;
    __syncthreads();
    if (t == 0) g_ksq[r] = sw[0] + sw[1] + sw[2] + sw[3];
}

// ---------------- 4: main HMMA flash kernel ----------------
// 128 CTAs: qb = bid>>1 (rows qb*128..+128), split = bid&1 (keys split*4096..+4096)
// 512 threads = 16 warps: 4 row-warps x 4 col-warps; warp tile 32 rows x 32 keys.
// K chunk = 128 keys, double-buffered; prefetch issued BEFORE the MMA.
// Each col-warp keeps its OWN running (m,s) per row; single final combine.
// ONE barrier per chunk.
__global__ void __launch_bounds__(512, 1) nce_main_kernel(){
    extern __shared__ __align__(16) uint8_t sm[];
    const uint32_t sb = smem_u32(sm);
    const int tid = threadIdx.x;
    const int lane = tid & 31, wid = tid >> 5;
    const int rw = wid >> 2, cw = wid & 3;      // row-warp (0..3), col-warp (0..3)
    const int g = lane >> 2, t = lane & 3;
    const int bid = blockIdx.x, qb = bid >> 1, split = bid & 1;
    const int m0 = qb << 7;
    const int kbase0 = split * 4096;
    // the single 128-key chunk containing this CTA's diagonals (or -1)
    const int diag_ch = ((qb >> 5) == split) ? (qb & 31) : -1;

    // ---- prologue: Q tile + chunk-0 K via cp.async ----
    for (int j = tid; j < 128*32; j += 512){
        int row = j >> 5, c = j & 31;
        cpa16(sb + OFF_QH + (uint32_t)(row*528 + c*16), &g_Qh[(size_t)(m0+row)*128 + c*4]);
        cpa16(sb + OFF_K0 + (uint32_t)(row*528 + c*16), &g_Kh[(size_t)(kbase0+row)*128 + c*4]);
    }
    if (tid < 32) cpa16(sb + OFF_KSQ + (uint32_t)(tid*16), &g_ksq[kbase0 + tid*4]);
    CP_COMMIT; CP_WAIT0;
    __syncthreads();

    float qs[2][2];
    #pragma unroll
    for (int mt = 0; mt < 2; mt++){
        qs[mt][0] = g_qsq[m0 + rw*32 + mt*16 + g];
        qs[mt][1] = g_qsq[m0 + rw*32 + mt*16 + g + 8];
    }

    const uint32_t a_off = sb + OFF_QH + (uint32_t)((rw*32 + (lane & 15))*528 + (lane >> 4)*16);
    const uint32_t b_off = (uint32_t)((cw*32 + (lane & 15))*528 + (lane >> 4)*16);

    // per-col-warp running (m,s) for the 4 row-halves this thread owns
    float mrun[2][2], srun[2][2];
    #pragma unroll
    for (int mt = 0; mt < 2; mt++)
        #pragma unroll
        for (int h = 0; h < 2; h++){ mrun[mt][h] = -INFINITY; srun[mt][h] = 0.f; }

    for (int ch = 0; ch < 32; ch++){
        const int buf = ch & 1;

        // prefetch next 128-key chunk into the other buffer (overlaps MMA+epilogue)
        if (ch < 31){
            const int bk = kbase0 + (ch + 1)*128;
            const uint32_t kdst = sb + (buf ? OFF_K0 : OFF_K1);
            for (int j = tid; j < 128*32; j += 512){
                int row = j >> 5, c = j & 31;
                cpa16(kdst + (uint32_t)(row*528 + c*16), &g_Kh[(size_t)(bk+row)*128 + c*4]);
            }
            if (tid < 32) cpa16(sb + OFF_KSQ + (uint32_t)((buf^1)*512 + tid*16),
                                &g_ksq[bk + tid*4]);
            CP_COMMIT;
        }

        // ---- single-pass bf16 MMA on current buffer ----
        float acc[2][4][4];
        #pragma unroll
        for (int mt = 0; mt < 2; mt++)
            #pragma unroll
            for (int nt = 0; nt < 4; nt++)
                #pragma unroll
                for (int q4 = 0; q4 < 4; q4++) acc[mt][nt][q4] = 0.f;

        const uint32_t bbase = sb + (buf ? OFF_K1 : OFF_K0) + b_off;
        #pragma unroll 4
        for (int kt = 0; kt < 16; kt++){
            uint32_t A[2][4];
            #pragma unroll
            for (int mt = 0; mt < 2; mt++)
                ldm_x4(A[mt][0], A[mt][1], A[mt][2], A[mt][3],
                       a_off + (uint32_t)(mt*16*528) + (uint32_t)(kt*32));
            uint32_t B0[4], B1[4];
            ldm_x4(B0[0], B0[1], B0[2], B0[3], bbase + (uint32_t)(kt*32));
            ldm_x4(B1[0], B1[1], B1[2], B1[3], bbase + (uint32_t)(16*528) + (uint32_t)(kt*32));
            #pragma unroll
            for (int mt = 0; mt < 2; mt++){
                mma_bf16(acc[mt][0], A[mt], B0[0], B0[2]);
                mma_bf16(acc[mt][1], A[mt], B0[1], B0[3]);
                mma_bf16(acc[mt][2], A[mt], B1[0], B1[2]);
                mma_bf16(acc[mt][3], A[mt], B1[1], B1[3]);
            }
        }

        // ---- epilogue: logits + per-row LOCAL online logsumexp (log2 domain) ----
        const float* ksq = (const float*)(sm + OFF_KSQ + buf*512);
        float kq[8];
        #pragma unroll
        for (int nt = 0; nt < 4; nt++){
            kq[nt*2]   = ksq[cw*32 + nt*8 + 2*t];
            kq[nt*2+1] = ksq[cw*32 + nt*8 + 2*t + 1];
        }
        const bool has_diag = (ch == diag_ch);
        #pragma unroll
        for (int mt = 0; mt < 2; mt++){
            #pragma unroll
            for (int h = 0; h < 2; h++){
                const int rloc = rw*32 + mt*16 + g + 8*h;
                float v[8];
                float vmax = -INFINITY;
                #pragma unroll
                for (int nt = 0; nt < 4; nt++){
                    #pragma unroll
                    for (int j = 0; j < 2; j++){
                        float sq = fmaf(acc[mt][nt][h*2 + j], -2.f, qs[mt][h] + kq[nt*2 + j]);
                        float lv = -sqrta(fmaxf(sq, 0.f)) * C_L2T;
                        v[nt*2 + j] = lv;
                        vmax = fmaxf(vmax, lv);
                    }
                }
                if (has_diag){   // diag key local col == rloc, 1 chunk in 32
                    #pragma unroll
                    for (int nt = 0; nt < 4; nt++)
                        #pragma unroll
                        for (int j = 0; j < 2; j++)
                            if (cw*32 + nt*8 + 2*t + j == rloc) g_pd[m0 + rloc] = v[nt*2 + j];
                }
                vmax = fmaxf(vmax, __shfl_xor_sync(0xffffffffu, vmax, 1));
                vmax = fmaxf(vmax, __shfl_xor_sync(0xffffffffu, vmax, 2));
                float s = 0.f;
                #pragma unroll
                for (int i = 0; i < 8; i++) s += ex2a(v[i] - vmax);
                s += __shfl_xor_sync(0xffffffffu, s, 1);
                s += __shfl_xor_sync(0xffffffffu, s, 2);
                // local running update (no smem, no barrier)
                float nm = fmaxf(mrun[mt][h], vmax);
                srun[mt][h] = srun[mt][h] * ex2a(fmaxf(mrun[mt][h] - nm, -126.f))
                            + s * ex2a(vmax - nm);
                mrun[mt][h] = nm;
            }
        }

        CP_WAIT0;          // next chunk resident
        __syncthreads();   // single barrier: guards K buffer rotation
    }

    // ---- final combine: 4 col-warp partials per row, once ----
    float2* part = (float2*)(sm + OFF_PART);
    if (t == 0){
        #pragma unroll
        for (int mt = 0; mt < 2; mt++)
            #pragma unroll
            for (int h = 0; h < 2; h++)
                part[cw*128 + rw*32 + mt*16 + g + 8*h] =
                    make_float2(mrun[mt][h], srun[mt][h]);
    }
    __syncthreads();
    if (cw == 0){
        const int rl = rw*32 + lane;
        float2 p0 = part[0*128 + rl];
        float2 p1 = part[1*128 + rl];
        float2 p2 = part[2*128 + rl];
        float2 p3 = part[3*128 + rl];
        float m = fmaxf(fmaxf(p0.x, p1.x), fmaxf(p2.x, p3.x));
        float s = p0.y * ex2a(fmaxf(p0.x - m, -126.f)) + p1.y * ex2a(fmaxf(p1.x - m, -126.f))
                + p2.y * ex2a(fmaxf(p2.x - m, -126.f)) + p3.y * ex2a(fmaxf(p3.x - m, -126.f));
        const int row = m0 + rl;
        g_pm[row*2 + split] = m;
        g_ps[row*2 + split] = s;
    }
}

// ---------------- 5: merge splits + mean ----------------
__global__ void fin_kernel(float* __restrict__ out){
    float acc = 0.f;
    for (int r = threadIdx.x; r < P; r += 256){
        float ma = g_pm[2*r], mb = g_pm[2*r + 1];
        float sa = g_ps[2*r], sb = g_ps[2*r + 1];
        float m = fmaxf(ma, mb);
        float s = sa * ex2a(fmaxf(ma - m, -126.f)) + sb * ex2a(fmaxf(mb - m, -126.f));
        acc += LN2F * (m + __log2f(s) - g_pd[r]);
    }
    #pragma unroll
    for (int o = 16; o; o >>= 1) acc += __shfl_xor_sync(0xffffffffu, acc, o);
    __shared__ float sw[8];
    if ((threadIdx.x & 31) == 0) sw[threadIdx.x >> 5] = acc;
    __syncthreads();
    if (threadIdx.x == 0){
        float tt = 0.f;
        #pragma unroll
        for (int i = 0; i < 8; i++) tt += sw[i];
        out[0] = tt / (float)P;
    }
}

extern "C" void kernel_launch(void* const* d_in, const int* in_sizes, int n_in,
                              void* d_out, int out_size){
    const float* f1  = (const float*)d_in[0];
    const float* f2  = (const float*)d_in[1];
    const void*  map = d_in[2];

    cudaFuncSetAttribute(nce_main_kernel,
                         cudaFuncAttributeMaxDynamicSharedMemorySize, SMEM_TOTAL);

    detect_kernel<<<1, 256>>>((const int*)map);    // launch 1
    prepQ_kernel<<<P, 128>>>(f1, map);             // launch 2
    prepK_kernel<<<P, 128>>>(f2);                  // launch 3
    nce_main_kernel<<<128, 512, SMEM_TOTAL>>>();   // launch 4 (ncu target)
    fin_kernel<<<1, 256>>>((float*)d_out);         // launch 5
}

// round 7
// speedup vs baseline: 8.7082x; 1.2641x over previous
#include <cuda_runtime.h>
#include <cuda_bf16.h>
#include <stdint.h>
#include <math.h>

#define P 8192
#define D 256
#define C_L2T 20.60992915555662f   // log2(e)/0.07
#define LN2F  0.6931471805599453f

// ---------------- device scratch (allocation-free) ----------------
__device__ int g_is64;
__device__ __align__(16) uint32_t g_Qh[P * 128];          // bf16x2 packed rows
// K in mma-B-fragment order: [kb(256)][kt(16)][u4(2)][lane(32)][4 u32] + 1KB pad
__device__ __align__(16) uint32_t g_Kf[256 * 4096 + 256];
// ksq in C-fragment order: [kb(256)][lane(32)][8 floats]
__device__ __align__(16) float g_ksqf[256 * 256];
__device__ float g_qsq[P];
__device__ float g_ksq[P];
__device__ float g_pm[P * 2];
__device__ float g_ps[P * 2];
__device__ float g_pd[P];

// ---------------- smem: Q tile (128 rows x 528B) + final-combine scratch ----------------
#define OFF_PART 67584           // float2[4][128] = 4096B
#define SMEM_TOTAL 71680

// ---------------- PTX helpers (base-PTX only, sm_103-safe) ----------------
__device__ __forceinline__ uint32_t smem_u32(const void* p){
    uint32_t a;
    asm("{ .reg .u64 t; cvta.to.shared.u64 t, %1; cvt.u32.u64 %0, t; }" : "=r"(a) : "l"(p));
    return a;
}
__device__ __forceinline__ void cpa16(uint32_t dst, const void* src){
    asm volatile("cp.async.cg.shared.global [%0], [%1], 16;" :: "r"(dst), "l"(src));
}
#define CP_COMMIT asm volatile("cp.async.commit_group;" ::: "memory")
#define CP_WAIT0  asm volatile("cp.async.wait_group 0;" ::: "memory")

__device__ __forceinline__ void ldm_x4(uint32_t& r0, uint32_t& r1, uint32_t& r2, uint32_t& r3,
                                       uint32_t addr){
    asm volatile("ldmatrix.sync.aligned.m8n8.x4.shared.b16 {%0,%1,%2,%3}, [%4];"
                 : "=r"(r0), "=r"(r1), "=r"(r2), "=r"(r3) : "r"(addr));
}
__device__ __forceinline__ void mma_bf16(float c[4], const uint32_t a[4],
                                         uint32_t b0, uint32_t b1){
    asm volatile(
        "mma.sync.aligned.m16n8k16.row.col.f32.bf16.bf16.f32 "
        "{%0,%1,%2,%3}, {%4,%5,%6,%7}, {%8,%9}, {%0,%1,%2,%3};"
        : "+f"(c[0]), "+f"(c[1]), "+f"(c[2]), "+f"(c[3])
        : "r"(a[0]), "r"(a[1]), "r"(a[2]), "r"(a[3]), "r"(b0), "r"(b1));
}
__device__ __forceinline__ float ex2a(float x){ float y; asm("ex2.approx.f32 %0, %1;" : "=f"(y) : "f"(x)); return y; }
__device__ __forceinline__ float sqrta(float x){ float y; asm("sqrt.approx.f32 %0, %1;" : "=f"(y) : "f"(x)); return y; }
__device__ __forceinline__ uint32_t f2bf_bits(float x){
    return (uint32_t)__bfloat16_as_ushort(__float2bfloat16(x));
}

// ---------------- 1: dtype detection (int64 vs int32 map) ----------------
__global__ void detect_kernel(const int* __restrict__ m32){
    __shared__ int nz;
    if (threadIdx.x == 0) nz = 0;
    __syncthreads();
    int any = 0;
    for (int i = 1 + 2*(int)threadIdx.x; i < P; i += 2*(int)blockDim.x)
        if (m32[i] != 0) any = 1;
    if (any) atomicOr(&nz, 1);
    __syncthreads();
    if (threadIdx.x == 0) g_is64 = (nz == 0) ? 1 : 0;
}

// ---------------- 2: gather Q -> bf16 pack + qsq + ksq (fused) ----------------
__global__ void prepQ_kernel(const float* __restrict__ f1, const float* __restrict__ f2,
                             const void* __restrict__ map){
    const int r = blockIdx.x, t = threadIdx.x;
    long long idx = g_is64 ? ((const long long*)map)[r]
                           : (long long)((const int*)map)[r];
    float2 q = reinterpret_cast<const float2*>(f1 + idx * (long long)D)[t];
    g_Qh[r*128 + t] = f2bf_bits(q.x) | (f2bf_bits(q.y) << 16);
    float2 k = reinterpret_cast<const float2*>(f2 + (long long)r * D)[t];
    float qs = q.x*q.x + q.y*q.y;
    float ks = k.x*k.x + k.y*k.y;
    #pragma unroll
    for (int o = 16; o; o >>= 1){
        qs += __shfl_xor_sync(0xffffffffu, qs, o);
        ks += __shfl_xor_sync(0xffffffffu, ks, o);
    }
    __shared__ float sq[4], sk[4];
    if ((t & 31) == 0){ sq[t >> 5] = qs; sk[t >> 5] = ks; }
    __syncthreads();
    if (t == 0){
        g_qsq[r] = sq[0] + sq[1] + sq[2] + sq[3];
        g_ksq[r] = sk[0] + sk[1] + sk[2] + sk[3];
    }
}

// ---------------- 3: pack K into mma B-fragment layout + fragment-ordered ksq ----------------
// PTX m16n8k16 B fragment: lane L holds b0 = B[k=2(L%4)+{0,1}, n=L/4], b1 = same k+8.
// uint4 layout index: kb*1024 + kt*64 + u4*32 + lane ; u4 packs (nt0,nt1) then (nt2,nt3).
__global__ void prepKf_kernel(const float* __restrict__ f2){
    const int kb = blockIdx.x;
    for (int idx = threadIdx.x; idx < 4096; idx += 256){
        int kt  = idx >> 8;
        int rem = idx & 255;
        int u4  = rem >> 7;
        int lam = (rem >> 2) & 31;
        int p   = rem & 3;
        int nt  = u4*2 + (p >> 1);
        int w   = p & 1;
        int n = kb*32 + nt*8 + (lam >> 2);
        int k = kt*16 + w*8 + (lam & 3)*2;
        const float* src = f2 + (long long)n * D + k;
        g_Kf[kb*4096 + idx] = f2bf_bits(src[0]) | (f2bf_bits(src[1]) << 16);
    }
    {   // ksq fragment: [kb][lane][nt*2+j] = ksq[kb*32 + nt*8 + 2*(lane%4) + j]
        int lam = threadIdx.x >> 3, i = threadIdx.x & 7;
        int nt = i >> 1, j = i & 1;
        g_ksqf[kb*256 + threadIdx.x] = g_ksq[kb*32 + nt*8 + (lam & 3)*2 + j];
    }
}

// ---------------- 4: main HMMA kernel, K streamed from L2 via fragment LDG ----------------
// 128 CTAs: qb = bid>>1 (rows qb*128..+128), split = bid&1 (keys split*4096..+4096).
// 512 threads = 16 warps: 4 row-warps x 4 col-warps. Warp tile 32 rows x 32 keys.
// Col-warp cw sweeps kb = split*128 + cw*32 .. +32 (32 chunks), fully independently:
// NO barriers, NO K smem, linear B pointer (+1KB per kt step).
__global__ void __launch_bounds__(512, 1) nce_main_kernel(){
    extern __shared__ __align__(16) uint8_t sm[];
    const uint32_t sb = smem_u32(sm);
    const int tid = threadIdx.x;
    const int lane = tid & 31, wid = tid >> 5;
    const int rw = wid >> 2, cw = wid & 3;
    const int g = lane >> 2, t = lane & 3;
    const int bid = blockIdx.x, qb = bid >> 1, split = bid & 1;
    const int m0 = qb << 7;
    const int kb0 = split*128 + cw*32;
    const int diag_kb = qb*4 + rw;      // global 32-key block holding this row-warp's diagonal

    // ---- prologue: Q tile into smem ----
    for (int j = tid; j < 128*32; j += 512){
        int row = j >> 5, c = j & 31;
        cpa16(sb + (uint32_t)(row*528 + c*16), &g_Qh[(size_t)(m0+row)*128 + c*4]);
    }
    CP_COMMIT; CP_WAIT0;
    __syncthreads();

    float qs[2][2];
    #pragma unroll
    for (int mt = 0; mt < 2; mt++){
        qs[mt][0] = g_qsq[m0 + rw*32 + mt*16 + g];
        qs[mt][1] = g_qsq[m0 + rw*32 + mt*16 + g + 8];
    }

    const uint32_t a_base = sb + (uint32_t)((rw*32 + (lane & 15))*528 + (lane >> 4)*16);
    const uint4* bp  = reinterpret_cast<const uint4*>(g_Kf) + (size_t)kb0*1024 + lane;
    const float4* kp = reinterpret_cast<const float4*>(g_ksqf) + (size_t)kb0*64 + lane*2;

    // preload first kt of first chunk
    uint4 blo = __ldg(bp), bhi = __ldg(bp + 32);
    bp += 64;

    float mrun[2][2], srun[2][2];
    #pragma unroll
    for (int mt = 0; mt < 2; mt++)
        #pragma unroll
        for (int h = 0; h < 2; h++){ mrun[mt][h] = -INFINITY; srun[mt][h] = 0.f; }

    for (int c = 0; c < 32; c++){
        // ksq for this chunk (ready by epilogue time)
        float4 kq0 = __ldg(kp), kq1 = __ldg(kp + 1);
        kp += 64;

        float acc[2][4][4];
        #pragma unroll
        for (int mt = 0; mt < 2; mt++)
            #pragma unroll
            for (int nt = 0; nt < 4; nt++)
                #pragma unroll
                for (int q4 = 0; q4 < 4; q4++) acc[mt][nt][q4] = 0.f;

        #pragma unroll
        for (int kt = 0; kt < 16; kt++){
            uint4 clo = blo, chi = bhi;
            // prefetch next kt / next chunk's kt0 (array padded: last load is in-bounds)
            blo = __ldg(bp); bhi = __ldg(bp + 32);
            bp += 64;
            uint32_t A0[4], A1[4];
            ldm_x4(A0[0], A0[1], A0[2], A0[3], a_base + (uint32_t)(kt*32));
            ldm_x4(A1[0], A1[1], A1[2], A1[3], a_base + (uint32_t)(16*528 + kt*32));
            mma_bf16(acc[0][0], A0, clo.x, clo.y);
            mma_bf16(acc[0][1], A0, clo.z, clo.w);
            mma_bf16(acc[0][2], A0, chi.x, chi.y);
            mma_bf16(acc[0][3], A0, chi.z, chi.w);
            mma_bf16(acc[1][0], A1, clo.x, clo.y);
            mma_bf16(acc[1][1], A1, clo.z, clo.w);
            mma_bf16(acc[1][2], A1, chi.x, chi.y);
            mma_bf16(acc[1][3], A1, chi.z, chi.w);
        }

        // ---- epilogue: per-thread online logsumexp (log2 domain), no shuffles ----
        float kq[8] = {kq0.x, kq0.y, kq0.z, kq0.w, kq1.x, kq1.y, kq1.z, kq1.w};
        const bool has_diag = ((kb0 + c) == diag_kb);
        #pragma unroll
        for (int mt = 0; mt < 2; mt++){
            #pragma unroll
            for (int h = 0; h < 2; h++){
                const int rloc = rw*32 + mt*16 + g + 8*h;
                float v[8];
                float vmax = -INFINITY;
                #pragma unroll
                for (int nt = 0; nt < 4; nt++){
                    #pragma unroll
                    for (int j = 0; j < 2; j++){
                        float sq = fmaf(acc[mt][nt][h*2 + j], -2.f, qs[mt][h] + kq[nt*2 + j]);
                        float lv = -sqrta(fmaxf(sq, 0.f)) * C_L2T;
                        v[nt*2 + j] = lv;
                        vmax = fmaxf(vmax, lv);
                    }
                }
                if (has_diag){
                    #pragma unroll
                    for (int nt = 0; nt < 4; nt++)
                        #pragma unroll
                        for (int j = 0; j < 2; j++)
                            if (nt*8 + 2*t + j == mt*16 + g + 8*h)
                                g_pd[m0 + rloc] = v[nt*2 + j];
                }
                float s = 0.f;
                #pragma unroll
                for (int i = 0; i < 8; i++) s += ex2a(v[i] - vmax);
                float nm = fmaxf(mrun[mt][h], vmax);
                srun[mt][h] = srun[mt][h] * ex2a(fmaxf(mrun[mt][h] - nm, -126.f))
                            + s * ex2a(vmax - nm);
                mrun[mt][h] = nm;
            }
        }
    }

    // ---- merge across t lanes (once), then across col-warps via smem ----
    float2* part = (float2*)(sm + OFF_PART);
    #pragma unroll
    for (int mt = 0; mt < 2; mt++){
        #pragma unroll
        for (int h = 0; h < 2; h++){
            float m = mrun[mt][h], s = srun[mt][h];
            #pragma unroll
            for (int o = 1; o <= 2; o <<= 1){
                float mo = __shfl_xor_sync(0xffffffffu, m, o);
                float so = __shfl_xor_sync(0xffffffffu, s, o);
                float nm = fmaxf(m, mo);
                s = s * ex2a(fmaxf(m - nm, -126.f)) + so * ex2a(fmaxf(mo - nm, -126.f));
                m = nm;
            }
            if (t == 0) part[cw*128 + rw*32 + mt*16 + g + 8*h] = make_float2(m, s);
        }
    }
    __syncthreads();
    if (cw == 0){
        const int rl = rw*32 + lane;
        float2 p0 = part[0*128 + rl];
        float2 p1 = part[1*128 + rl];
        float2 p2 = part[2*128 + rl];
        float2 p3 = part[3*128 + rl];
        float m = fmaxf(fmaxf(p0.x, p1.x), fmaxf(p2.x, p3.x));
        float s = p0.y * ex2a(fmaxf(p0.x - m, -126.f)) + p1.y * ex2a(fmaxf(p1.x - m, -126.f))
                + p2.y * ex2a(fmaxf(p2.x - m, -126.f)) + p3.y * ex2a(fmaxf(p3.x - m, -126.f));
        const int row = m0 + rl;
        g_pm[row*2 + split] = m;
        g_ps[row*2 + split] = s;
    }
}

// ---------------- 5: merge splits + mean ----------------
__global__ void fin_kernel(float* __restrict__ out){
    float acc = 0.f;
    for (int r = threadIdx.x; r < P; r += 256){
        float ma = g_pm[2*r], mb = g_pm[2*r + 1];
        float sa = g_ps[2*r], sb = g_ps[2*r + 1];
        float m = fmaxf(ma, mb);
        float s = sa * ex2a(fmaxf(ma - m, -126.f)) + sb * ex2a(fmaxf(mb - m, -126.f));
        acc += LN2F * (m + __log2f(s) - g_pd[r]);
    }
    #pragma unroll
    for (int o = 16; o; o >>= 1) acc += __shfl_xor_sync(0xffffffffu, acc, o);
    __shared__ float sw[8];
    if ((threadIdx.x & 31) == 0) sw[threadIdx.x >> 5] = acc;
    __syncthreads();
    if (threadIdx.x == 0){
        float tt = 0.f;
        #pragma unroll
        for (int i = 0; i < 8; i++) tt += sw[i];
        out[0] = tt / (float)P;
    }
}

extern "C" void kernel_launch(void* const* d_in, const int* in_sizes, int n_in,
                              void* d_out, int out_size){
    const float* f1  = (const float*)d_in[0];
    const float* f2  = (const float*)d_in[1];
    const void*  map = d_in[2];

    cudaFuncSetAttribute(nce_main_kernel,
                         cudaFuncAttributeMaxDynamicSharedMemorySize, SMEM_TOTAL);

    detect_kernel<<<1, 256>>>((const int*)map);    // launch 1
    prepQ_kernel<<<P, 128>>>(f1, f2, map);         // launch 2 (Q pack + qsq + ksq)
    prepKf_kernel<<<256, 256>>>(f2);               // launch 3 (fragment pack)
    nce_main_kernel<<<128, 512, SMEM_TOTAL>>>();   // launch 4 (ncu target)
    fin_kernel<<<1, 256>>>((float*)d_out);         // launch 5
}

// round 8
// speedup vs baseline: 8.7322x; 1.0028x over previous
#include <cuda_runtime.h>
#include <cuda_bf16.h>
#include <stdint.h>
#include <math.h>

#define P 8192
#define D 256
#define C_L2T 20.60992915555662f   // log2(e)/0.07
#define LN2F  0.6931471805599453f

// ---------------- device scratch (allocation-free) ----------------
__device__ int g_is64;
__device__ __align__(16) uint32_t g_Qh[P * 128];          // bf16x2 packed rows
// K in mma-B-fragment order: [kb(256)][kt(16)][u4(2)][lane(32)][4 u32] + pad
__device__ __align__(16) uint32_t g_Kf[256 * 4096 + 256];
// ksq in C-fragment order: [kb(256)][lane(32)][8 floats]
__device__ __align__(16) float g_ksqf[256 * 256];
__device__ float g_qsq[P];
__device__ float g_ksq[P];
__device__ float g_pm[P * 2];
__device__ float g_ps[P * 2];
__device__ float g_pd[P];

// ---------------- smem: Q tile (128 rows x 528B) + final-combine scratch ----------------
#define OFF_PART 67584           // float2[4][128] = 4096B
#define SMEM_TOTAL 71680

// ---------------- PTX helpers (base-PTX only, sm_103-safe) ----------------
__device__ __forceinline__ uint32_t smem_u32(const void* p){
    uint32_t a;
    asm("{ .reg .u64 t; cvta.to.shared.u64 t, %1; cvt.u32.u64 %0, t; }" : "=r"(a) : "l"(p));
    return a;
}
__device__ __forceinline__ void cpa16(uint32_t dst, const void* src){
    asm volatile("cp.async.cg.shared.global [%0], [%1], 16;" :: "r"(dst), "l"(src));
}
#define CP_COMMIT asm volatile("cp.async.commit_group;" ::: "memory")
#define CP_WAIT0  asm volatile("cp.async.wait_group 0;" ::: "memory")

__device__ __forceinline__ void ldm_x4(uint32_t& r0, uint32_t& r1, uint32_t& r2, uint32_t& r3,
                                       uint32_t addr){
    asm volatile("ldmatrix.sync.aligned.m8n8.x4.shared.b16 {%0,%1,%2,%3}, [%4];"
                 : "=r"(r0), "=r"(r1), "=r"(r2), "=r"(r3) : "r"(addr));
}
__device__ __forceinline__ void mma_bf16(float c[4], const uint32_t a[4],
                                         uint32_t b0, uint32_t b1){
    asm volatile(
        "mma.sync.aligned.m16n8k16.row.col.f32.bf16.bf16.f32 "
        "{%0,%1,%2,%3}, {%4,%5,%6,%7}, {%8,%9}, {%0,%1,%2,%3};"
        : "+f"(c[0]), "+f"(c[1]), "+f"(c[2]), "+f"(c[3])
        : "r"(a[0]), "r"(a[1]), "r"(a[2]), "r"(a[3]), "r"(b0), "r"(b1));
}
__device__ __forceinline__ float ex2a(float x){ float y; asm("ex2.approx.f32 %0, %1;" : "=f"(y) : "f"(x)); return y; }
__device__ __forceinline__ float sqrta(float x){ float y; asm("sqrt.approx.f32 %0, %1;" : "=f"(y) : "f"(x)); return y; }
__device__ __forceinline__ uint32_t f2bf_bits(float x){
    return (uint32_t)__bfloat16_as_ushort(__float2bfloat16(x));
}

// ---------------- 1: dtype detection (int64 vs int32 map) ----------------
__global__ void detect_kernel(const int* __restrict__ m32){
    __shared__ int nz;
    if (threadIdx.x == 0) nz = 0;
    __syncthreads();
    int any = 0;
    for (int i = 1 + 2*(int)threadIdx.x; i < P; i += 2*(int)blockDim.x)
        if (m32[i] != 0) any = 1;
    if (any) atomicOr(&nz, 1);
    __syncthreads();
    if (threadIdx.x == 0) g_is64 = (nz == 0) ? 1 : 0;
}

// ---------------- 2: gather Q -> bf16 pack + qsq + ksq (fused) ----------------
__global__ void prepQ_kernel(const float* __restrict__ f1, const float* __restrict__ f2,
                             const void* __restrict__ map){
    const int r = blockIdx.x, t = threadIdx.x;
    long long idx = g_is64 ? ((const long long*)map)[r]
                           : (long long)((const int*)map)[r];
    float2 q = reinterpret_cast<const float2*>(f1 + idx * (long long)D)[t];
    g_Qh[r*128 + t] = f2bf_bits(q.x) | (f2bf_bits(q.y) << 16);
    float2 k = reinterpret_cast<const float2*>(f2 + (long long)r * D)[t];
    float qs = q.x*q.x + q.y*q.y;
    float ks = k.x*k.x + k.y*k.y;
    #pragma unroll
    for (int o = 16; o; o >>= 1){
        qs += __shfl_xor_sync(0xffffffffu, qs, o);
        ks += __shfl_xor_sync(0xffffffffu, ks, o);
    }
    __shared__ float sq[4], sk[4];
    if ((t & 31) == 0){ sq[t >> 5] = qs; sk[t >> 5] = ks; }
    __syncthreads();
    if (t == 0){
        g_qsq[r] = sq[0] + sq[1] + sq[2] + sq[3];
        g_ksq[r] = sk[0] + sk[1] + sk[2] + sk[3];
    }
}

// ---------------- 3: pack K into mma B-fragment layout + fragment-ordered ksq ----------------
// PTX m16n8k16 B fragment: lane L holds b0 = B[k=2(L%4)+{0,1}, n=L/4], b1 = same k+8.
// uint4 layout index: kb*1024 + kt*64 + u4*32 + lane ; u4 packs (nt0,nt1) then (nt2,nt3).
__global__ void prepKf_kernel(const float* __restrict__ f2){
    const int kb = blockIdx.x;
    for (int idx = threadIdx.x; idx < 4096; idx += 256){
        int kt  = idx >> 8;
        int rem = idx & 255;
        int u4  = rem >> 7;
        int lam = (rem >> 2) & 31;
        int p   = rem & 3;
        int nt  = u4*2 + (p >> 1);
        int w   = p & 1;
        int n = kb*32 + nt*8 + (lam >> 2);
        int k = kt*16 + w*8 + (lam & 3)*2;
        const float* src = f2 + (long long)n * D + k;
        g_Kf[kb*4096 + idx] = f2bf_bits(src[0]) | (f2bf_bits(src[1]) << 16);
    }
    {   // ksq fragment: [kb][lane][nt*2+j] = ksq[kb*32 + nt*8 + 2*(lane%4) + j]
        int lam = threadIdx.x >> 3, i = threadIdx.x & 7;
        int nt = i >> 1, j = i & 1;
        g_ksqf[kb*256 + threadIdx.x] = g_ksq[kb*32 + nt*8 + (lam & 3)*2 + j];
    }
}

// ---------------- 4: main HMMA kernel, K streamed from L2 via fragment LDG ----------------
// 128 CTAs: qb = bid>>1 (rows qb*128..+128), split = bid&1 (keys split*4096..+4096).
// 512 threads = 16 warps: 4 row-warps x 4 col-warps. Warp tile 32 rows x 32 keys.
// Col-warp cw sweeps kb = split*128 + cw*32 .. +32 (32 chunks) independently.
// PHASE STAGGER: warps sharing an SMSP (same cw) start their sweep at chunk rw*8,
// so MMA of one warp overlaps the epilogue of its SMSP siblings.
__global__ void __launch_bounds__(512, 1) nce_main_kernel(){
    extern __shared__ __align__(16) uint8_t sm[];
    const uint32_t sb = smem_u32(sm);
    const int tid = threadIdx.x;
    const int lane = tid & 31, wid = tid >> 5;
    const int rw = wid >> 2, cw = wid & 3;
    const int g = lane >> 2, t = lane & 3;
    const int bid = blockIdx.x, qb = bid >> 1, split = bid & 1;
    const int m0 = qb << 7;
    const int kb0 = split*128 + cw*32;
    const int diag_kb = qb*4 + rw;      // global 32-key block holding this row-warp's diagonal
    const int cstart = rw << 3;         // phase stagger: 8 chunks apart per SMSP sibling

    // ---- prologue: Q tile into smem ----
    for (int j = tid; j < 128*32; j += 512){
        int row = j >> 5, c = j & 31;
        cpa16(sb + (uint32_t)(row*528 + c*16), &g_Qh[(size_t)(m0+row)*128 + c*4]);
    }
    CP_COMMIT; CP_WAIT0;
    __syncthreads();

    float qs[2][2];
    #pragma unroll
    for (int mt = 0; mt < 2; mt++){
        qs[mt][0] = g_qsq[m0 + rw*32 + mt*16 + g];
        qs[mt][1] = g_qsq[m0 + rw*32 + mt*16 + g + 8];
    }

    const uint32_t a_base = sb + (uint32_t)((rw*32 + (lane & 15))*528 + (lane >> 4)*16);
    const uint4*  Bb = reinterpret_cast<const uint4*>(g_Kf);
    const float4* Kb = reinterpret_cast<const float4*>(g_ksqf);

    // preload kt0 of the first (staggered) chunk
    {
        const uint4* p0 = Bb + (size_t)(kb0 + cstart)*1024 + lane;
        // fallthrough into loop below with registers primed
        // (declared here, used in loop)
    }
    uint4 blo, bhi;
    {
        const uint4* p0 = Bb + (size_t)(kb0 + cstart)*1024 + lane;
        blo = __ldg(p0); bhi = __ldg(p0 + 32);
    }

    float mrun[2][2], srun[2][2];
    #pragma unroll
    for (int mt = 0; mt < 2; mt++)
        #pragma unroll
        for (int h = 0; h < 2; h++){ mrun[mt][h] = -INFINITY; srun[mt][h] = 0.f; }

    for (int i = 0; i < 32; i++){
        const int c  = (cstart + i) & 31;
        const int nc = (cstart + i + 1) & 31;      // next chunk (wraps; i=31 value unused)
        const int kb = kb0 + c;

        // ksq for this chunk (ready by epilogue time)
        const float4* kp = Kb + (size_t)kb*64 + lane*2;
        float4 kq0 = __ldg(kp), kq1 = __ldg(kp + 1);

        const uint4* bp = Bb + (size_t)kb*1024 + lane + 64;          // kt1 of this chunk
        const uint4* npc = Bb + (size_t)(kb0 + nc)*1024 + lane;      // kt0 of next chunk

        float acc[2][4][4];
        #pragma unroll
        for (int mt = 0; mt < 2; mt++)
            #pragma unroll
            for (int nt = 0; nt < 4; nt++)
                #pragma unroll
                for (int q4 = 0; q4 < 4; q4++) acc[mt][nt][q4] = 0.f;

        #pragma unroll
        for (int kt = 0; kt < 16; kt++){
            uint4 clo = blo, chi = bhi;
            // prefetch next kt; at kt==15 preload NEXT chunk's kt0 (full chunk early)
            const uint4* np = (kt == 15) ? npc : bp;
            blo = __ldg(np); bhi = __ldg(np + 32);
            bp += 64;
            uint32_t A0[4], A1[4];
            ldm_x4(A0[0], A0[1], A0[2], A0[3], a_base + (uint32_t)(kt*32));
            ldm_x4(A1[0], A1[1], A1[2], A1[3], a_base + (uint32_t)(16*528 + kt*32));
            mma_bf16(acc[0][0], A0, clo.x, clo.y);
            mma_bf16(acc[0][1], A0, clo.z, clo.w);
            mma_bf16(acc[0][2], A0, chi.x, chi.y);
            mma_bf16(acc[0][3], A0, chi.z, chi.w);
            mma_bf16(acc[1][0], A1, clo.x, clo.y);
            mma_bf16(acc[1][1], A1, clo.z, clo.w);
            mma_bf16(acc[1][2], A1, chi.x, chi.y);
            mma_bf16(acc[1][3], A1, chi.z, chi.w);
        }

        // ---- epilogue: per-thread online logsumexp (log2 domain), no shuffles ----
        float kq[8] = {kq0.x, kq0.y, kq0.z, kq0.w, kq1.x, kq1.y, kq1.z, kq1.w};
        const bool has_diag = (kb == diag_kb);
        #pragma unroll
        for (int mt = 0; mt < 2; mt++){
            #pragma unroll
            for (int h = 0; h < 2; h++){
                const int rloc = rw*32 + mt*16 + g + 8*h;
                float v[8];
                float vmax = -INFINITY;
                #pragma unroll
                for (int nt = 0; nt < 4; nt++){
                    #pragma unroll
                    for (int j = 0; j < 2; j++){
                        float sq = fmaf(acc[mt][nt][h*2 + j], -2.f, qs[mt][h] + kq[nt*2 + j]);
                        float lv = -sqrta(fmaxf(sq, 0.f)) * C_L2T;
                        v[nt*2 + j] = lv;
                        vmax = fmaxf(vmax, lv);
                    }
                }
                if (has_diag){
                    #pragma unroll
                    for (int nt = 0; nt < 4; nt++)
                        #pragma unroll
                        for (int j = 0; j < 2; j++)
                            if (nt*8 + 2*t + j == mt*16 + g + 8*h)
                                g_pd[m0 + rloc] = v[nt*2 + j];
                }
                float s = 0.f;
                #pragma unroll
                for (int i2 = 0; i2 < 8; i2++) s += ex2a(v[i2] - vmax);
                float nm = fmaxf(mrun[mt][h], vmax);
                srun[mt][h] = srun[mt][h] * ex2a(fmaxf(mrun[mt][h] - nm, -126.f))
                            + s * ex2a(vmax - nm);
                mrun[mt][h] = nm;
            }
        }
    }

    // ---- merge across t lanes (once), then across col-warps via smem ----
    float2* part = (float2*)(sm + OFF_PART);
    #pragma unroll
    for (int mt = 0; mt < 2; mt++){
        #pragma unroll
        for (int h = 0; h < 2; h++){
            float m = mrun[mt][h], s = srun[mt][h];
            #pragma unroll
            for (int o = 1; o <= 2; o <<= 1){
                float mo = __shfl_xor_sync(0xffffffffu, m, o);
                float so = __shfl_xor_sync(0xffffffffu, s, o);
                float nm = fmaxf(m, mo);
                s = s * ex2a(fmaxf(m - nm, -126.f)) + so * ex2a(fmaxf(mo - nm, -126.f));
                m = nm;
            }
            if (t == 0) part[cw*128 + rw*32 + mt*16 + g + 8*h] = make_float2(m, s);
        }
    }
    __syncthreads();
    if (cw == 0){
        const int rl = rw*32 + lane;
        float2 p0 = part[0*128 + rl];
        float2 p1 = part[1*128 + rl];
        float2 p2 = part[2*128 + rl];
        float2 p3 = part[3*128 + rl];
        float m = fmaxf(fmaxf(p0.x, p1.x), fmaxf(p2.x, p3.x));
        float s = p0.y * ex2a(fmaxf(p0.x - m, -126.f)) + p1.y * ex2a(fmaxf(p1.x - m, -126.f))
                + p2.y * ex2a(fmaxf(p2.x - m, -126.f)) + p3.y * ex2a(fmaxf(p3.x - m, -126.f));
        const int row = m0 + rl;
        g_pm[row*2 + split] = m;
        g_ps[row*2 + split] = s;
    }
}

// ---------------- 5: merge splits + mean ----------------
__global__ void fin_kernel(float* __restrict__ out){
    float acc = 0.f;
    for (int r = threadIdx.x; r < P; r += 256){
        float ma = g_pm[2*r], mb = g_pm[2*r + 1];
        float sa = g_ps[2*r], sb = g_ps[2*r + 1];
        float m = fmaxf(ma, mb);
        float s = sa * ex2a(fmaxf(ma - m, -126.f)) + sb * ex2a(fmaxf(mb - m, -126.f));
        acc += LN2F * (m + __log2f(s) - g_pd[r]);
    }
    #pragma unroll
    for (int o = 16; o; o >>= 1) acc += __shfl_xor_sync(0xffffffffu, acc, o);
    __shared__ float sw[8];
    if ((threadIdx.x & 31) == 0) sw[threadIdx.x >> 5] = acc;
    __syncthreads();
    if (threadIdx.x == 0){
        float tt = 0.f;
        #pragma unroll
        for (int i = 0; i < 8; i++) tt += sw[i];
        out[0] = tt / (float)P;
    }
}

extern "C" void kernel_launch(void* const* d_in, const int* in_sizes, int n_in,
                              void* d_out, int out_size){
    const float* f1  = (const float*)d_in[0];
    const float* f2  = (const float*)d_in[1];
    const void*  map = d_in[2];

    cudaFuncSetAttribute(nce_main_kernel,
                         cudaFuncAttributeMaxDynamicSharedMemorySize, SMEM_TOTAL);

    detect_kernel<<<1, 256>>>((const int*)map);    // launch 1
    prepQ_kernel<<<P, 128>>>(f1, f2, map);         // launch 2 (Q pack + qsq + ksq)
    prepKf_kernel<<<256, 256>>>(f2);               // launch 3 (fragment pack)
    nce_main_kernel<<<128, 512, SMEM_TOTAL>>>();   // launch 4 (ncu target)
    fin_kernel<<<1, 256>>>((float*)d_out);         // launch 5
}